// round 5
// baseline (speedup 1.0000x reference)
#include <cuda_runtime.h>
#include <cuda_fp16.h>
#include <math.h>
#include <stdint.h>

// ---------------------------------------------------------------------------
// TinyTransformer on GB300 (sm_103a): fp16x3 mma.sync GEMMs + flash attention.
// T=1024, B=4, D=1024, H=16, DQK=DV=64, FF=4096, L=4.
// tcgen05 is unavailable (harness PTX target is compute_103, arch-specific
// instructions rejected) -> legacy HMMA path, optimized.
// ---------------------------------------------------------------------------

constexpr int Tn   = 1024;
constexpr int Bn   = 4;
constexpr int Dn   = 1024;
constexpr int Hn   = 16;
constexpr int FFn  = 4096;
constexpr int Ln   = 4;
constexpr int NTOK = Tn * Bn;       // 4096
constexpr int HDQK = Hn * 64;       // 1024
constexpr int QKVN = 3 * HDQK;      // 3072 fused K|Q|V

// ------------------------- device scratch (no allocs) ----------------------
__device__ float g_x  [NTOK * Dn];
__device__ float g_z  [NTOK * Dn];
__device__ float g_f  [NTOK * Dn];
__device__ float g_att[NTOK * HDQK];

__device__ __half g_xh[NTOK * Dn],  g_xl[NTOK * Dn];
__device__ __half g_zh[NTOK * Dn],  g_zl[NTOK * Dn];
__device__ __half g_hh[NTOK * FFn], g_hl[NTOK * FFn];
__device__ __half g_qkvh[NTOK * QKVN], g_qkvl[NTOK * QKVN];

__device__ __half g_wqkvh[Ln * Dn * QKVN], g_wqkvl[Ln * Dn * QKVN];
__device__ __half g_w1h[Ln * Dn * FFn],  g_w1l[Ln * Dn * FFn];
__device__ __half g_w2h[Ln * FFn * Dn],  g_w2l[Ln * FFn * Dn];
__device__ float g_bqkv[Ln * QKVN];

// ------------------------- PTX helpers -------------------------------------
#define CP16(dst, src) \
    asm volatile("cp.async.cg.shared.global [%0], [%1], 16;" :: "r"(dst), "l"(src))
#define CP_COMMIT asm volatile("cp.async.commit_group;")
#define CP_WAIT1  asm volatile("cp.async.wait_group 1;")
#define CP_WAIT0  asm volatile("cp.async.wait_group 0;")

__device__ __forceinline__ void ldsm4(uint32_t* r, uint32_t a) {
    asm volatile("ldmatrix.sync.aligned.m8n8.x4.shared.b16 {%0,%1,%2,%3}, [%4];"
                 : "=r"(r[0]), "=r"(r[1]), "=r"(r[2]), "=r"(r[3]) : "r"(a));
}
__device__ __forceinline__ void ldsm4t(uint32_t* r, uint32_t a) {
    asm volatile("ldmatrix.sync.aligned.m8n8.x4.trans.shared.b16 {%0,%1,%2,%3}, [%4];"
                 : "=r"(r[0]), "=r"(r[1]), "=r"(r[2]), "=r"(r[3]) : "r"(a));
}
__device__ __forceinline__ void mma16816(float* c, const uint32_t* a,
                                         uint32_t b0, uint32_t b1) {
    asm volatile(
        "mma.sync.aligned.m16n8k16.row.col.f32.f16.f16.f32 "
        "{%0,%1,%2,%3}, {%4,%5,%6,%7}, {%8,%9}, {%0,%1,%2,%3};"
        : "+f"(c[0]), "+f"(c[1]), "+f"(c[2]), "+f"(c[3])
        : "r"(a[0]), "r"(a[1]), "r"(a[2]), "r"(a[3]), "r"(b0), "r"(b1));
}

__device__ __forceinline__ void splitf(float v, __half& h, __half& l) {
    h = __float2half_rn(v);
    l = __float2half_rn(v - __half2float(h));
}
__device__ __forceinline__ uint32_t pack2(__half a, __half b) {
    __half2 v; v.x = a; v.y = b;
    return *(uint32_t*)&v;
}

// ------------------------- fp32 -> split-fp16 reformat -----------------------
__global__ void __launch_bounds__(256)
cvt_pair_kernel(const float* __restrict__ src, __half* __restrict__ hi,
                __half* __restrict__ lo, int n4) {
    int i = blockIdx.x * blockDim.x + threadIdx.x;
    if (i >= n4) return;
    float4 v = ((const float4*)src)[i];
    __half2 h0, h1, l0, l1;
    splitf(v.x, h0.x, l0.x);
    splitf(v.y, h0.y, l0.y);
    splitf(v.z, h1.x, l1.x);
    splitf(v.w, h1.y, l1.y);
    ((__half2*)hi)[i * 2]     = h0;
    ((__half2*)hi)[i * 2 + 1] = h1;
    ((__half2*)lo)[i * 2]     = l0;
    ((__half2*)lo)[i * 2 + 1] = l1;
}

// Wk/Wq/Wv [L][Dn][1024] -> fused planes [L][Dn][3072] (K at 0, Q at 1024, V 2048)
__global__ void __launch_bounds__(256)
cvt_qkv_kernel(const float* __restrict__ Wk, const float* __restrict__ Wq,
               const float* __restrict__ Wv,
               __half* __restrict__ hi, __half* __restrict__ lo) {
    const int tsel = blockIdx.y;
    const float* src = (tsel == 0) ? Wk : (tsel == 1) ? Wq : Wv;
    int i = blockIdx.x * 256 + threadIdx.x;       // float4 index over L*Dn*1024/4
    float4 v = ((const float4*)src)[i];
    int e  = i * 4;
    int lk = e >> 10;              // l*Dn + k
    int n  = e & 1023;
    size_t o = (size_t)lk * QKVN + (tsel << 10) + n;
    __half2 h0, h1, l0, l1;
    splitf(v.x, h0.x, l0.x);
    splitf(v.y, h0.y, l0.y);
    splitf(v.z, h1.x, l1.x);
    splitf(v.w, h1.y, l1.y);
    *(__half2*)(hi + o)     = h0;
    *(__half2*)(hi + o + 2) = h1;
    *(__half2*)(lo + o)     = l0;
    *(__half2*)(lo + o + 2) = l1;
}

__global__ void __launch_bounds__(256)
combine_bias_kernel(const float* __restrict__ bk, const float* __restrict__ bq,
                    const float* __restrict__ bv, float* __restrict__ out) {
    int i = blockIdx.x * 256 + threadIdx.x;      // L*3072 total
    int l = i / QKVN, r = i % QKVN;
    float v;
    if (r < 1024)      v = bk[l * 1024 + r];
    else if (r < 2048) v = bq[l * 1024 + r - 1024];
    else               v = bv[l * 1024 + r - 2048];
    out[i] = v;
}

// ------------------------- fp16x3 tensor-core GEMM ---------------------------
// C[M,N] = A[M,K] @ B[K,N] + bias.  A/B split hi/lo fp16 planes (row-major).
// MODE 1: relu + split out.  MODE 2: relu + fp32 out.  MODE 3: split out.
// One __syncthreads per k-chunk; mma issued term-major (no RAW chains).
constexpr int BM = 128, BN = 128, BK = 32;
constexpr int ASTR = 80;
constexpr int BSTR = 272;
constexpr int A_BYTES = 128 * ASTR;
constexpr int B_BYTES = 32 * BSTR;
constexpr int STAGE   = 2 * A_BYTES + 2 * B_BYTES;
constexpr int GEMM_SMEM = 2 * STAGE;

template<int MODE>
__global__ void __launch_bounds__(256, 1)
gemm_mma_kernel(const __half* __restrict__ Ah, const __half* __restrict__ Al,
                const __half* __restrict__ Bh, const __half* __restrict__ Bl,
                const float* __restrict__ bias,
                float* __restrict__ Cf,
                __half* __restrict__ Ch, __half* __restrict__ Cl,
                int M, int K, int N) {
    extern __shared__ char smem[];
    const uint32_t sb = (uint32_t)__cvta_generic_to_shared(smem);
    const int t    = threadIdx.x;
    const int row0 = blockIdx.y * BM;
    const int col0 = blockIdx.x * BN;

    const int am = t >> 1, asel = t & 1;
    const int bk = t >> 3, bsel = t & 7;
    const __half* agh = Ah + (size_t)(row0 + am) * K + asel * 16;
    const __half* agl = Al + (size_t)(row0 + am) * K + asel * 16;
    const __half* bgh = Bh + (size_t)bk * N + col0 + bsel * 16;
    const __half* bgl = Bl + (size_t)bk * N + col0 + bsel * 16;
    const uint32_t adst = sb + am * ASTR + asel * 32;
    const uint32_t bdst = sb + 2 * A_BYTES + bk * BSTR + bsel * 32;

#define LOAD_STAGE(kt, s) do {                                                 \
    uint32_t so = (uint32_t)(s) * STAGE;                                       \
    size_t ko  = (size_t)(kt) * BK;                                            \
    size_t kon = ko * N;                                                       \
    CP16(adst + so,                agh + ko);                                  \
    CP16(adst + so + 16,           agh + ko + 8);                              \
    CP16(adst + so + A_BYTES,      agl + ko);                                  \
    CP16(adst + so + A_BYTES + 16, agl + ko + 8);                              \
    CP16(bdst + so,                bgh + kon);                                 \
    CP16(bdst + so + 16,           bgh + kon + 8);                             \
    CP16(bdst + so + B_BYTES,      bgl + kon);                                 \
    CP16(bdst + so + B_BYTES + 16, bgl + kon + 8);                             \
    CP_COMMIT;                                                                 \
} while (0)

    const int lane = t & 31, wid = t >> 5;
    const int wm = wid >> 2, wn = wid & 3;
    const uint32_t afo = (uint32_t)((wm * 64 + ((lane >> 3) & 1) * 8 + (lane & 7)) * ASTR
                                    + (lane >> 4) * 16);
    const uint32_t bfo = (uint32_t)((((lane >> 3) & 1) * 8 + (lane & 7)) * BSTR
                                    + (wn * 32 + (lane >> 4) * 8) * 2);

    float acc[4][4][4];
#pragma unroll
    for (int i = 0; i < 4; i++)
#pragma unroll
        for (int j = 0; j < 4; j++)
#pragma unroll
            for (int r = 0; r < 4; r++) acc[i][j][r] = 0.f;

    LOAD_STAGE(0, 0);
    const int KT = K / BK;
    for (int kt = 0; kt < KT; kt++) {
        CP_WAIT0;            // stage kt&1 data landed
        __syncthreads();     // all warps done reading stage (kt+1)&1 (prev iter)
        if (kt + 1 < KT) LOAD_STAGE(kt + 1, (kt + 1) & 1);

        const uint32_t so   = (uint32_t)(kt & 1) * STAGE;
        const uint32_t ah_b = sb + so + afo;
        const uint32_t al_b = ah_b + A_BYTES;
        const uint32_t bh_b = sb + so + 2 * A_BYTES + bfo;
        const uint32_t bl_b = bh_b + B_BYTES;

#pragma unroll
        for (int ks = 0; ks < 2; ks++) {
            uint32_t ahi[4][4], alo[4][4], bhi[4][2], blo[4][2];
#pragma unroll
            for (int i = 0; i < 4; i++) {
                ldsm4(ahi[i], ah_b + i * (16 * ASTR) + ks * 32);
                ldsm4(alo[i], al_b + i * (16 * ASTR) + ks * 32);
            }
#pragma unroll
            for (int j2 = 0; j2 < 2; j2++) {
                uint32_t r[4];
                ldsm4t(r, bh_b + ks * (16 * BSTR) + j2 * 32);
                bhi[j2 * 2][0] = r[0]; bhi[j2 * 2][1] = r[1];
                bhi[j2 * 2 + 1][0] = r[2]; bhi[j2 * 2 + 1][1] = r[3];
                ldsm4t(r, bl_b + ks * (16 * BSTR) + j2 * 32);
                blo[j2 * 2][0] = r[0]; blo[j2 * 2][1] = r[1];
                blo[j2 * 2 + 1][0] = r[2]; blo[j2 * 2 + 1][1] = r[3];
            }
            // term-major: 16 independent accumulators between reuses
#pragma unroll
            for (int i = 0; i < 4; i++)
#pragma unroll
                for (int j = 0; j < 4; j++)
                    mma16816(acc[i][j], ahi[i], bhi[j][0], bhi[j][1]);
#pragma unroll
            for (int i = 0; i < 4; i++)
#pragma unroll
                for (int j = 0; j < 4; j++)
                    mma16816(acc[i][j], ahi[i], blo[j][0], blo[j][1]);
#pragma unroll
            for (int i = 0; i < 4; i++)
#pragma unroll
                for (int j = 0; j < 4; j++)
                    mma16816(acc[i][j], alo[i], bhi[j][0], bhi[j][1]);
        }
    }
#undef LOAD_STAGE

    const int rb = row0 + wm * 64 + (lane >> 2);
    const int cb = col0 + wn * 32 + (lane & 3) * 2;
#pragma unroll
    for (int i = 0; i < 4; i++) {
#pragma unroll
        for (int j = 0; j < 4; j++) {
            const int r = rb + i * 16;
            const int c = cb + j * 8;
            const float2 bb = *(const float2*)(bias + c);
            float v0 = acc[i][j][0] + bb.x;
            float v1 = acc[i][j][1] + bb.y;
            float v2 = acc[i][j][2] + bb.x;
            float v3 = acc[i][j][3] + bb.y;
            if (MODE == 1 || MODE == 2) {
                v0 = fmaxf(v0, 0.f); v1 = fmaxf(v1, 0.f);
                v2 = fmaxf(v2, 0.f); v3 = fmaxf(v3, 0.f);
            }
            if (MODE == 1 || MODE == 3) {
                __half2 h, l;
                splitf(v0, h.x, l.x); splitf(v1, h.y, l.y);
                *(__half2*)(Ch + (size_t)r * N + c) = h;
                *(__half2*)(Cl + (size_t)r * N + c) = l;
                splitf(v2, h.x, l.x); splitf(v3, h.y, l.y);
                *(__half2*)(Ch + (size_t)(r + 8) * N + c) = h;
                *(__half2*)(Cl + (size_t)(r + 8) * N + c) = l;
            } else {
                float2 o0 = {v0, v1}, o1 = {v2, v3};
                *(float2*)(Cf + (size_t)r * N + c) = o0;
                *(float2*)(Cf + (size_t)(r + 8) * N + c) = o1;
            }
        }
    }
}

// ------------------------- resnorm ------------------------------------------
__global__ void __launch_bounds__(256)
resnorm_kernel(const float* __restrict__ X, const float* __restrict__ FX,
               float* __restrict__ OUT,
               __half* __restrict__ OH, __half* __restrict__ OL) {
    __shared__ float s1[8];
    __shared__ float s2[8];
    const int row = blockIdx.x;
    const size_t base = (size_t)row * Dn;
    const int t = threadIdx.x;

    float v[4];
    float sum = 0.f;
#pragma unroll
    for (int i = 0; i < 4; i++) {
        int d = t + i * 256;
        v[i] = X[base + d] + FX[base + d];
        sum += v[i];
    }
#pragma unroll
    for (int o = 16; o > 0; o >>= 1) sum += __shfl_xor_sync(0xffffffffu, sum, o);
    if ((t & 31) == 0) s1[t >> 5] = sum;
    __syncthreads();
    float tot = 0.f;
#pragma unroll
    for (int w = 0; w < 8; w++) tot += s1[w];
    const float mu = tot * (1.0f / 1024.0f);

    float sq = 0.f;
#pragma unroll
    for (int i = 0; i < 4; i++) { float d = v[i] - mu; sq += d * d; }
#pragma unroll
    for (int o = 16; o > 0; o >>= 1) sq += __shfl_xor_sync(0xffffffffu, sq, o);
    if ((t & 31) == 0) s2[t >> 5] = sq;
    __syncthreads();
    float tots = 0.f;
#pragma unroll
    for (int w = 0; w < 8; w++) tots += s2[w];
    const float sd  = sqrtf(tots * (1.0f / 1023.0f));
    const float inv = 1.0f / (sd + 1e-6f);

#pragma unroll
    for (int i = 0; i < 4; i++) {
        const int d = t + i * 256;
        const float val = (v[i] - mu) * inv;
        OUT[base + d] = val;
        __half h, l;
        splitf(val, h, l);
        OH[base + d] = h;
        OL[base + d] = l;
    }
}

// ------------------------- fp16x3 flash attention ----------------------------
// QKV fused buffer: row stride QKVN; K at col 0, Q at 1024, V at 2048.
constexpr int ATT_K_BYTES  = 128 * 144;
constexpr int ATT_QV_TILE  = 64 * 144;
constexpr int ATT_QV_STAGE = 4 * ATT_QV_TILE;
constexpr int ATT_QV_BASE  = 2 * ATT_K_BYTES;
constexpr int ATT2_SMEM    = ATT_QV_BASE + 2 * ATT_QV_STAGE;

__device__ __forceinline__ void attn_load_qv(
    uint32_t sb, int stage, int j0, int b, int h, int t,
    const __half* __restrict__ Qh, const __half* __restrict__ Ql,
    const __half* __restrict__ Vh, const __half* __restrict__ Vl) {
#pragma unroll
    for (int i = 0; i < 8; i++) {
        int c   = t + i * 256;
        int tp  = c >> 9;
        int row = (c >> 3) & 63;
        int seg = c & 7;
        const __half* base = (tp == 0) ? Qh : (tp == 1) ? Ql
                           : (tp == 2) ? Vh : Vl;
        const __half* src =
            base + ((size_t)(j0 + row) * Bn + b) * QKVN + h * 64 + seg * 8;
        uint32_t dst = sb + ATT_QV_BASE + (uint32_t)stage * ATT_QV_STAGE
                     + tp * ATT_QV_TILE + row * 144 + seg * 16;
        CP16(dst, src);
    }
}

__global__ void __launch_bounds__(256, 1)
attn_mma_kernel(const __half* __restrict__ QKVh, const __half* __restrict__ QKVl,
                float* __restrict__ Ob) {
    extern __shared__ char smem[];
    const uint32_t sb = (uint32_t)__cvta_generic_to_shared(smem);
    const int bh = blockIdx.y, b = bh / Hn, h = bh % Hn;
    const int i0 = blockIdx.x * 128;
    const int t = threadIdx.x, lane = t & 31, wid = t >> 5;

    const __half* Kh = QKVh;
    const __half* Kl = QKVl;
    const __half* Qh = QKVh + 1024;
    const __half* Ql = QKVl + 1024;
    const __half* Vh = QKVh + 2048;
    const __half* Vl = QKVl + 2048;

#pragma unroll
    for (int i = 0; i < 8; i++) {
        int c     = t + i * 256;
        int plane = c >> 10;
        int row   = (c >> 3) & 127;
        int seg   = c & 7;
        const __half* src = (plane ? Kl : Kh)
            + ((size_t)(i0 + row) * Bn + b) * QKVN + h * 64 + seg * 8;
        CP16(sb + plane * ATT_K_BYTES + row * 144 + seg * 16, src);
    }
    CP_COMMIT;
    attn_load_qv(sb, 0, 0, b, h, t, Qh, Ql, Vh, Vl);
    CP_COMMIT;

    CP_WAIT1;
    __syncthreads();

    uint32_t akh[4][4], akl[4][4];
    const uint32_t ka = sb + (uint32_t)((wid * 16 + ((lane >> 3) & 1) * 8 + (lane & 7)) * 144
                                        + (lane >> 4) * 16);
#pragma unroll
    for (int ks = 0; ks < 4; ks++) {
        ldsm4(akh[ks], ka + ks * 32);
        ldsm4(akl[ks], ka + ATT_K_BYTES + ks * 32);
    }

    float m0 = -1e30f, m1 = -1e30f, l0 = 0.f, l1 = 0.f;
    float o[8][4];
#pragma unroll
    for (int n = 0; n < 8; n++)
#pragma unroll
        for (int r = 0; r < 4; r++) o[n][r] = 0.f;

    const uint32_t qoff = (uint32_t)(((lane >> 4) * 8 + (lane & 7)) * 144
                                     + ((lane >> 3) & 1) * 16);
    const uint32_t voff = (uint32_t)((((lane >> 3) & 1) * 8 + (lane & 7)) * 144
                                     + (lane >> 4) * 16);
    const float scl = 0.03125f;

    for (int kt = 0; kt < 16; kt++) {
        if (kt < 15) {
            attn_load_qv(sb, (kt + 1) & 1, (kt + 1) * 64, b, h, t, Qh, Ql, Vh, Vl);
            CP_COMMIT;
            CP_WAIT1;
        } else {
            CP_WAIT0;
        }
        __syncthreads();
        const uint32_t qvb = sb + ATT_QV_BASE + (uint32_t)(kt & 1) * ATT_QV_STAGE;

        float s[8][4];
#pragma unroll
        for (int n = 0; n < 8; n++)
#pragma unroll
            for (int r = 0; r < 4; r++) s[n][r] = 0.f;

#pragma unroll
        for (int ks = 0; ks < 4; ks++) {
#pragma unroll
            for (int np = 0; np < 4; np++) {
                uint32_t qh[4], ql[4];
                const uint32_t qa = qvb + qoff + np * (16 * 144) + ks * 32;
                ldsm4(qh, qa);
                ldsm4(ql, qa + ATT_QV_TILE);
                mma16816(s[2 * np],     akh[ks], qh[0], qh[1]);
                mma16816(s[2 * np + 1], akh[ks], qh[2], qh[3]);
                mma16816(s[2 * np],     akh[ks], ql[0], ql[1]);
                mma16816(s[2 * np + 1], akh[ks], ql[2], ql[3]);
                mma16816(s[2 * np],     akl[ks], qh[0], qh[1]);
                mma16816(s[2 * np + 1], akl[ks], qh[2], qh[3]);
            }
        }

        float mt0 = -1e30f, mt1 = -1e30f;
#pragma unroll
        for (int n = 0; n < 8; n++) {
            s[n][0] *= scl; s[n][1] *= scl; s[n][2] *= scl; s[n][3] *= scl;
            mt0 = fmaxf(mt0, fmaxf(s[n][0], s[n][1]));
            mt1 = fmaxf(mt1, fmaxf(s[n][2], s[n][3]));
        }
        mt0 = fmaxf(mt0, __shfl_xor_sync(0xffffffffu, mt0, 1));
        mt0 = fmaxf(mt0, __shfl_xor_sync(0xffffffffu, mt0, 2));
        mt1 = fmaxf(mt1, __shfl_xor_sync(0xffffffffu, mt1, 1));
        mt1 = fmaxf(mt1, __shfl_xor_sync(0xffffffffu, mt1, 2));
        const float mn0 = fmaxf(m0, mt0), mn1 = fmaxf(m1, mt1);
        const float rs0 = __expf(m0 - mn0), rs1 = __expf(m1 - mn1);
        m0 = mn0; m1 = mn1;

        float ps0 = 0.f, ps1 = 0.f;
#pragma unroll
        for (int n = 0; n < 8; n++) {
            s[n][0] = __expf(s[n][0] - mn0);
            s[n][1] = __expf(s[n][1] - mn0);
            s[n][2] = __expf(s[n][2] - mn1);
            s[n][3] = __expf(s[n][3] - mn1);
            ps0 += s[n][0] + s[n][1];
            ps1 += s[n][2] + s[n][3];
        }
        ps0 += __shfl_xor_sync(0xffffffffu, ps0, 1);
        ps0 += __shfl_xor_sync(0xffffffffu, ps0, 2);
        ps1 += __shfl_xor_sync(0xffffffffu, ps1, 1);
        ps1 += __shfl_xor_sync(0xffffffffu, ps1, 2);
        l0 = l0 * rs0 + ps0;
        l1 = l1 * rs1 + ps1;
#pragma unroll
        for (int n = 0; n < 8; n++) {
            o[n][0] *= rs0; o[n][1] *= rs0;
            o[n][2] *= rs1; o[n][3] *= rs1;
        }

#pragma unroll
        for (int ki = 0; ki < 4; ki++) {
            __half hv[8], lv[8];
            splitf(s[2 * ki][0],     hv[0], lv[0]);
            splitf(s[2 * ki][1],     hv[1], lv[1]);
            splitf(s[2 * ki][2],     hv[2], lv[2]);
            splitf(s[2 * ki][3],     hv[3], lv[3]);
            splitf(s[2 * ki + 1][0], hv[4], lv[4]);
            splitf(s[2 * ki + 1][1], hv[5], lv[5]);
            splitf(s[2 * ki + 1][2], hv[6], lv[6]);
            splitf(s[2 * ki + 1][3], hv[7], lv[7]);
            uint32_t ph[4], pl[4];
            ph[0] = pack2(hv[0], hv[1]); ph[1] = pack2(hv[2], hv[3]);
            ph[2] = pack2(hv[4], hv[5]); ph[3] = pack2(hv[6], hv[7]);
            pl[0] = pack2(lv[0], lv[1]); pl[1] = pack2(lv[2], lv[3]);
            pl[2] = pack2(lv[4], lv[5]); pl[3] = pack2(lv[6], lv[7]);

#pragma unroll
            for (int np = 0; np < 4; np++) {
                uint32_t vh[4], vl[4];
                const uint32_t va = qvb + 2 * ATT_QV_TILE + voff
                                  + ki * (16 * 144) + np * 32;
                ldsm4t(vh, va);
                ldsm4t(vl, va + ATT_QV_TILE);
                mma16816(o[2 * np],     ph, vh[0], vh[1]);
                mma16816(o[2 * np + 1], ph, vh[2], vh[3]);
                mma16816(o[2 * np],     ph, vl[0], vl[1]);
                mma16816(o[2 * np + 1], ph, vl[2], vl[3]);
                mma16816(o[2 * np],     pl, vh[0], vh[1]);
                mma16816(o[2 * np + 1], pl, vh[2], vh[3]);
            }
        }
        __syncthreads();
    }

    const float inv0 = 1.0f / l0, inv1 = 1.0f / l1;
    const int row0 = i0 + wid * 16 + (lane >> 2);
    const int colb = h * 64 + (lane & 3) * 2;
#pragma unroll
    for (int n = 0; n < 8; n++) {
        float2 w0 = {o[n][0] * inv0, o[n][1] * inv0};
        float2 w1 = {o[n][2] * inv1, o[n][3] * inv1};
        *(float2*)(Ob + ((size_t)row0 * Bn + b) * HDQK + colb + n * 8) = w0;
        *(float2*)(Ob + ((size_t)(row0 + 8) * Bn + b) * HDQK + colb + n * 8) = w1;
    }
}

// ------------------------- host driver --------------------------------------
extern "C" void kernel_launch(void* const* d_in, const int* in_sizes, int n_in,
                              void* d_out, int out_size) {
    (void)in_sizes; (void)n_in; (void)out_size;

    const float* x_in = (const float*)d_in[0];
    const float* Wk = (const float*)d_in[2];
    const float* bk = (const float*)d_in[3];
    const float* Wq = (const float*)d_in[4];
    const float* bq = (const float*)d_in[5];
    const float* Wv = (const float*)d_in[6];
    const float* bv = (const float*)d_in[7];
    const float* W1 = (const float*)d_in[8];
    const float* b1 = (const float*)d_in[9];
    const float* W2 = (const float*)d_in[10];
    const float* b2 = (const float*)d_in[11];

    float *px, *pz, *pf, *pa, *pbq;
    cudaGetSymbolAddress((void**)&px, g_x);
    cudaGetSymbolAddress((void**)&pz, g_z);
    cudaGetSymbolAddress((void**)&pf, g_f);
    cudaGetSymbolAddress((void**)&pa, g_att);
    cudaGetSymbolAddress((void**)&pbq, g_bqkv);

    __half *xh, *xl, *zh, *zl, *hh, *hl, *qkh, *qkl;
    __half *wqh, *wql, *w1h, *w1l, *w2h, *w2l;
    cudaGetSymbolAddress((void**)&xh, g_xh);   cudaGetSymbolAddress((void**)&xl, g_xl);
    cudaGetSymbolAddress((void**)&zh, g_zh);   cudaGetSymbolAddress((void**)&zl, g_zl);
    cudaGetSymbolAddress((void**)&hh, g_hh);   cudaGetSymbolAddress((void**)&hl, g_hl);
    cudaGetSymbolAddress((void**)&qkh, g_qkvh); cudaGetSymbolAddress((void**)&qkl, g_qkvl);
    cudaGetSymbolAddress((void**)&wqh, g_wqkvh); cudaGetSymbolAddress((void**)&wql, g_wqkvl);
    cudaGetSymbolAddress((void**)&w1h, g_w1h);   cudaGetSymbolAddress((void**)&w1l, g_w1l);
    cudaGetSymbolAddress((void**)&w2h, g_w2h);   cudaGetSymbolAddress((void**)&w2l, g_w2l);

    cudaFuncSetAttribute(gemm_mma_kernel<1>,
                         cudaFuncAttributeMaxDynamicSharedMemorySize, GEMM_SMEM);
    cudaFuncSetAttribute(gemm_mma_kernel<2>,
                         cudaFuncAttributeMaxDynamicSharedMemorySize, GEMM_SMEM);
    cudaFuncSetAttribute(gemm_mma_kernel<3>,
                         cudaFuncAttributeMaxDynamicSharedMemorySize, GEMM_SMEM);
    cudaFuncSetAttribute(attn_mma_kernel,
                         cudaFuncAttributeMaxDynamicSharedMemorySize, ATT2_SMEM);

    const dim3 blk(256);

    // exactly 5 setup launches so ncu (-s 5 -c 1) captures the first GEMM
    cvt_pair_kernel<<<NTOK * Dn / 1024, blk>>>(x_in, xh, xl, NTOK * Dn / 4);
    cvt_qkv_kernel<<<dim3(Ln * Dn * 1024 / 1024, 3), blk>>>(Wk, Wq, Wv, wqh, wql);
    cvt_pair_kernel<<<Ln * Dn * FFn / 1024, blk>>>(W1, w1h, w1l, Ln * Dn * FFn / 4);
    cvt_pair_kernel<<<Ln * FFn * Dn / 1024, blk>>>(W2, w2h, w2l, Ln * FFn * Dn / 4);
    combine_bias_kernel<<<Ln * QKVN / 256, blk>>>(bk, bq, bv, pbq);

    const dim3 gFF1(FFn / BN, NTOK / BM);    // (32, 32)
    const dim3 gFF2(Dn  / BN, NTOK / BM);    // (8, 32)
    const dim3 gQKV(QKVN / BN, NTOK / BM);   // (24, 32)
    const dim3 gATT(Tn / 128, Bn * Hn);      // (8, 64)

    for (int l = 0; l < Ln; l++) {
        const float* xl32 = (l == 0) ? x_in : px;

        gemm_mma_kernel<1><<<gFF1, blk, GEMM_SMEM>>>(
            xh, xl, w1h + (size_t)l * Dn * FFn, w1l + (size_t)l * Dn * FFn,
            b1 + (size_t)l * FFn, nullptr, hh, hl, NTOK, Dn, FFn);
        gemm_mma_kernel<2><<<gFF2, blk, GEMM_SMEM>>>(
            hh, hl, w2h + (size_t)l * FFn * Dn, w2l + (size_t)l * FFn * Dn,
            b2 + (size_t)l * Dn, pf, nullptr, nullptr, NTOK, FFn, Dn);

        resnorm_kernel<<<NTOK, blk>>>(xl32, pf, pz, zh, zl);

        gemm_mma_kernel<3><<<gQKV, blk, GEMM_SMEM>>>(
            zh, zl, wqh + (size_t)l * Dn * QKVN, wql + (size_t)l * Dn * QKVN,
            pbq + (size_t)l * QKVN, nullptr, qkh, qkl, NTOK, Dn, QKVN);

        attn_mma_kernel<<<gATT, blk, ATT2_SMEM>>>(qkh, qkl, pa);

        float* xout = (l == Ln - 1) ? (float*)d_out : px;
        resnorm_kernel<<<NTOK, blk>>>(pz, pa, xout, xh, xl);
    }
}

// round 6
// speedup vs baseline: 1.5097x; 1.5097x over previous
#include <cuda_runtime.h>
#include <cuda_fp16.h>
#include <math.h>
#include <stdint.h>

// ---------------------------------------------------------------------------
// TinyTransformer on GB300 (sm_103a): fp16x3 mma.sync GEMMs + flash attention.
// T=1024, B=4, D=1024, H=16, DQK=DV=64, FF=4096, L=4.
// tcgen05 unavailable in this harness (PTX target compute_103) -> HMMA path.
// GEMM: 3-stage cp.async pipeline with EARLY ISSUE (loads enqueued before the
// wait) -- round-5's late-issue schedule exposed memory latency and regressed.
// ---------------------------------------------------------------------------

constexpr int Tn   = 1024;
constexpr int Bn   = 4;
constexpr int Dn   = 1024;
constexpr int Hn   = 16;
constexpr int FFn  = 4096;
constexpr int Ln   = 4;
constexpr int NTOK = Tn * Bn;       // 4096
constexpr int HDQK = Hn * 64;       // 1024
constexpr int QKVN = 3 * HDQK;      // 3072 fused K|Q|V

// ------------------------- device scratch (no allocs) ----------------------
__device__ float g_x  [NTOK * Dn];
__device__ float g_z  [NTOK * Dn];
__device__ float g_f  [NTOK * Dn];
__device__ float g_att[NTOK * HDQK];

__device__ __half g_xh[NTOK * Dn],  g_xl[NTOK * Dn];
__device__ __half g_zh[NTOK * Dn],  g_zl[NTOK * Dn];
__device__ __half g_hh[NTOK * FFn], g_hl[NTOK * FFn];
__device__ __half g_qkvh[NTOK * QKVN], g_qkvl[NTOK * QKVN];

__device__ __half g_wqkvh[Ln * Dn * QKVN], g_wqkvl[Ln * Dn * QKVN];
__device__ __half g_w1h[Ln * Dn * FFn],  g_w1l[Ln * Dn * FFn];
__device__ __half g_w2h[Ln * FFn * Dn],  g_w2l[Ln * FFn * Dn];
__device__ float g_bqkv[Ln * QKVN];

// ------------------------- PTX helpers -------------------------------------
#define CP16(dst, src) \
    asm volatile("cp.async.cg.shared.global [%0], [%1], 16;" :: "r"(dst), "l"(src))
#define CP_COMMIT asm volatile("cp.async.commit_group;")
#define CP_WAIT2  asm volatile("cp.async.wait_group 2;")
#define CP_WAIT1  asm volatile("cp.async.wait_group 1;")
#define CP_WAIT0  asm volatile("cp.async.wait_group 0;")

__device__ __forceinline__ void ldsm4(uint32_t* r, uint32_t a) {
    asm volatile("ldmatrix.sync.aligned.m8n8.x4.shared.b16 {%0,%1,%2,%3}, [%4];"
                 : "=r"(r[0]), "=r"(r[1]), "=r"(r[2]), "=r"(r[3]) : "r"(a));
}
__device__ __forceinline__ void ldsm4t(uint32_t* r, uint32_t a) {
    asm volatile("ldmatrix.sync.aligned.m8n8.x4.trans.shared.b16 {%0,%1,%2,%3}, [%4];"
                 : "=r"(r[0]), "=r"(r[1]), "=r"(r[2]), "=r"(r[3]) : "r"(a));
}
__device__ __forceinline__ void mma16816(float* c, const uint32_t* a,
                                         uint32_t b0, uint32_t b1) {
    asm volatile(
        "mma.sync.aligned.m16n8k16.row.col.f32.f16.f16.f32 "
        "{%0,%1,%2,%3}, {%4,%5,%6,%7}, {%8,%9}, {%0,%1,%2,%3};"
        : "+f"(c[0]), "+f"(c[1]), "+f"(c[2]), "+f"(c[3])
        : "r"(a[0]), "r"(a[1]), "r"(a[2]), "r"(a[3]), "r"(b0), "r"(b1));
}

__device__ __forceinline__ void splitf(float v, __half& h, __half& l) {
    h = __float2half_rn(v);
    l = __float2half_rn(v - __half2float(h));
}
__device__ __forceinline__ uint32_t pack2(__half a, __half b) {
    __half2 v; v.x = a; v.y = b;
    return *(uint32_t*)&v;
}

// ------------------------- fp32 -> split-fp16 reformat -----------------------
__global__ void __launch_bounds__(256)
cvt_pair_kernel(const float* __restrict__ src, __half* __restrict__ hi,
                __half* __restrict__ lo, int n4) {
    int i = blockIdx.x * blockDim.x + threadIdx.x;
    if (i >= n4) return;
    float4 v = ((const float4*)src)[i];
    __half2 h0, h1, l0, l1;
    splitf(v.x, h0.x, l0.x);
    splitf(v.y, h0.y, l0.y);
    splitf(v.z, h1.x, l1.x);
    splitf(v.w, h1.y, l1.y);
    ((__half2*)hi)[i * 2]     = h0;
    ((__half2*)hi)[i * 2 + 1] = h1;
    ((__half2*)lo)[i * 2]     = l0;
    ((__half2*)lo)[i * 2 + 1] = l1;
}

// Wk/Wq/Wv [L][Dn][1024] -> fused planes [L][Dn][3072]
__global__ void __launch_bounds__(256)
cvt_qkv_kernel(const float* __restrict__ Wk, const float* __restrict__ Wq,
               const float* __restrict__ Wv,
               __half* __restrict__ hi, __half* __restrict__ lo) {
    const int tsel = blockIdx.y;
    const float* src = (tsel == 0) ? Wk : (tsel == 1) ? Wq : Wv;
    int i = blockIdx.x * 256 + threadIdx.x;
    float4 v = ((const float4*)src)[i];
    int e  = i * 4;
    int lk = e >> 10;
    int n  = e & 1023;
    size_t o = (size_t)lk * QKVN + (tsel << 10) + n;
    __half2 h0, h1, l0, l1;
    splitf(v.x, h0.x, l0.x);
    splitf(v.y, h0.y, l0.y);
    splitf(v.z, h1.x, l1.x);
    splitf(v.w, h1.y, l1.y);
    *(__half2*)(hi + o)     = h0;
    *(__half2*)(hi + o + 2) = h1;
    *(__half2*)(lo + o)     = l0;
    *(__half2*)(lo + o + 2) = l1;
}

__global__ void __launch_bounds__(256)
combine_bias_kernel(const float* __restrict__ bk, const float* __restrict__ bq,
                    const float* __restrict__ bv, float* __restrict__ out) {
    int i = blockIdx.x * 256 + threadIdx.x;
    int l = i / QKVN, r = i % QKVN;
    float v;
    if (r < 1024)      v = bk[l * 1024 + r];
    else if (r < 2048) v = bq[l * 1024 + r - 1024];
    else               v = bv[l * 1024 + r - 2048];
    out[i] = v;
}

// ------------------------- fp16x3 tensor-core GEMM ---------------------------
// MODE 1: relu + split out.  MODE 2: relu + fp32 out.  MODE 3: split out.
constexpr int BM = 128, BN = 128, BK = 32;
constexpr int ASTR = 80;
constexpr int BSTR = 272;
constexpr int A_BYTES = 128 * ASTR;
constexpr int B_BYTES = 32 * BSTR;
constexpr int STAGE   = 2 * A_BYTES + 2 * B_BYTES;   // 37888
constexpr int GEMM_SMEM = 3 * STAGE;                 // 113664

template<int MODE>
__global__ void __launch_bounds__(256, 1)
gemm_mma_kernel(const __half* __restrict__ Ah, const __half* __restrict__ Al,
                const __half* __restrict__ Bh, const __half* __restrict__ Bl,
                const float* __restrict__ bias,
                float* __restrict__ Cf,
                __half* __restrict__ Ch, __half* __restrict__ Cl,
                int M, int K, int N) {
    extern __shared__ char smem[];
    const uint32_t sb = (uint32_t)__cvta_generic_to_shared(smem);
    const int t    = threadIdx.x;
    const int row0 = blockIdx.y * BM;
    const int col0 = blockIdx.x * BN;

    const int am = t >> 1, asel = t & 1;
    const int bk = t >> 3, bsel = t & 7;
    const __half* agh = Ah + (size_t)(row0 + am) * K + asel * 16;
    const __half* agl = Al + (size_t)(row0 + am) * K + asel * 16;
    const __half* bgh = Bh + (size_t)bk * N + col0 + bsel * 16;
    const __half* bgl = Bl + (size_t)bk * N + col0 + bsel * 16;
    const uint32_t adst = sb + am * ASTR + asel * 32;
    const uint32_t bdst = sb + 2 * A_BYTES + bk * BSTR + bsel * 32;

#define LOAD_STAGE(kt, s) do {                                                 \
    uint32_t so = (uint32_t)(s) * STAGE;                                       \
    size_t ko  = (size_t)(kt) * BK;                                            \
    size_t kon = ko * N;                                                       \
    CP16(adst + so,                agh + ko);                                  \
    CP16(adst + so + 16,           agh + ko + 8);                              \
    CP16(adst + so + A_BYTES,      agl + ko);                                  \
    CP16(adst + so + A_BYTES + 16, agl + ko + 8);                              \
    CP16(bdst + so,                bgh + kon);                                 \
    CP16(bdst + so + 16,           bgh + kon + 8);                             \
    CP16(bdst + so + B_BYTES,      bgl + kon);                                 \
    CP16(bdst + so + B_BYTES + 16, bgl + kon + 8);                             \
    CP_COMMIT;                                                                 \
} while (0)

    const int lane = t & 31, wid = t >> 5;
    const int wm = wid >> 2, wn = wid & 3;
    const uint32_t afo = (uint32_t)((wm * 64 + ((lane >> 3) & 1) * 8 + (lane & 7)) * ASTR
                                    + (lane >> 4) * 16);
    const uint32_t bfo = (uint32_t)((((lane >> 3) & 1) * 8 + (lane & 7)) * BSTR
                                    + (wn * 32 + (lane >> 4) * 8) * 2);

    float acc[4][4][4];
#pragma unroll
    for (int i = 0; i < 4; i++)
#pragma unroll
        for (int j = 0; j < 4; j++)
#pragma unroll
            for (int r = 0; r < 4; r++) acc[i][j][r] = 0.f;

    const int KT = K / BK;
    LOAD_STAGE(0, 0);
    LOAD_STAGE(1, 1);

    int s = 0, sload = 2;           // stage being computed / stage to load next
    for (int kt = 0; kt < KT; kt++) {
        // EARLY ISSUE: enqueue loads for kt+2 before waiting on stage kt.
        if (kt + 2 < KT) {
            LOAD_STAGE(kt + 2, sload);
            CP_WAIT2;               // stage kt arrived; kt+1, kt+2 in flight
        } else if (kt + 1 < KT) {
            CP_WAIT1;
        } else {
            CP_WAIT0;
        }
        __syncthreads();

        const uint32_t so   = (uint32_t)s * STAGE;
        const uint32_t ah_b = sb + so + afo;
        const uint32_t al_b = ah_b + A_BYTES;
        const uint32_t bh_b = sb + so + 2 * A_BYTES + bfo;
        const uint32_t bl_b = bh_b + B_BYTES;

#pragma unroll
        for (int ks = 0; ks < 2; ks++) {
            uint32_t ahi[4][4], alo[4][4], bhi[4][2], blo[4][2];
#pragma unroll
            for (int i = 0; i < 4; i++) {
                ldsm4(ahi[i], ah_b + i * (16 * ASTR) + ks * 32);
                ldsm4(alo[i], al_b + i * (16 * ASTR) + ks * 32);
            }
#pragma unroll
            for (int j2 = 0; j2 < 2; j2++) {
                uint32_t r[4];
                ldsm4t(r, bh_b + ks * (16 * BSTR) + j2 * 32);
                bhi[j2 * 2][0] = r[0]; bhi[j2 * 2][1] = r[1];
                bhi[j2 * 2 + 1][0] = r[2]; bhi[j2 * 2 + 1][1] = r[3];
                ldsm4t(r, bl_b + ks * (16 * BSTR) + j2 * 32);
                blo[j2 * 2][0] = r[0]; blo[j2 * 2][1] = r[1];
                blo[j2 * 2 + 1][0] = r[2]; blo[j2 * 2 + 1][1] = r[3];
            }
#pragma unroll
            for (int i = 0; i < 4; i++)
#pragma unroll
                for (int j = 0; j < 4; j++)
                    mma16816(acc[i][j], ahi[i], bhi[j][0], bhi[j][1]);
#pragma unroll
            for (int i = 0; i < 4; i++)
#pragma unroll
                for (int j = 0; j < 4; j++)
                    mma16816(acc[i][j], ahi[i], blo[j][0], blo[j][1]);
#pragma unroll
            for (int i = 0; i < 4; i++)
#pragma unroll
                for (int j = 0; j < 4; j++)
                    mma16816(acc[i][j], alo[i], bhi[j][0], bhi[j][1]);
        }
        __syncthreads();    // all warps done with stage s before it is reloaded

        s = (s == 2) ? 0 : s + 1;
        sload = (sload == 2) ? 0 : sload + 1;
    }
#undef LOAD_STAGE

    const int rb = row0 + wm * 64 + (lane >> 2);
    const int cb = col0 + wn * 32 + (lane & 3) * 2;
#pragma unroll
    for (int i = 0; i < 4; i++) {
#pragma unroll
        for (int j = 0; j < 4; j++) {
            const int r = rb + i * 16;
            const int c = cb + j * 8;
            const float2 bb = *(const float2*)(bias + c);
            float v0 = acc[i][j][0] + bb.x;
            float v1 = acc[i][j][1] + bb.y;
            float v2 = acc[i][j][2] + bb.x;
            float v3 = acc[i][j][3] + bb.y;
            if (MODE == 1 || MODE == 2) {
                v0 = fmaxf(v0, 0.f); v1 = fmaxf(v1, 0.f);
                v2 = fmaxf(v2, 0.f); v3 = fmaxf(v3, 0.f);
            }
            if (MODE == 1 || MODE == 3) {
                __half2 h, l;
                splitf(v0, h.x, l.x); splitf(v1, h.y, l.y);
                *(__half2*)(Ch + (size_t)r * N + c) = h;
                *(__half2*)(Cl + (size_t)r * N + c) = l;
                splitf(v2, h.x, l.x); splitf(v3, h.y, l.y);
                *(__half2*)(Ch + (size_t)(r + 8) * N + c) = h;
                *(__half2*)(Cl + (size_t)(r + 8) * N + c) = l;
            } else {
                float2 o0 = {v0, v1}, o1 = {v2, v3};
                *(float2*)(Cf + (size_t)r * N + c) = o0;
                *(float2*)(Cf + (size_t)(r + 8) * N + c) = o1;
            }
        }
    }
}

// ------------------------- resnorm ------------------------------------------
__global__ void __launch_bounds__(256)
resnorm_kernel(const float* __restrict__ X, const float* __restrict__ FX,
               float* __restrict__ OUT,
               __half* __restrict__ OH, __half* __restrict__ OL) {
    __shared__ float s1[8];
    __shared__ float s2[8];
    const int row = blockIdx.x;
    const size_t base = (size_t)row * Dn;
    const int t = threadIdx.x;

    float v[4];
    float sum = 0.f;
#pragma unroll
    for (int i = 0; i < 4; i++) {
        int d = t + i * 256;
        v[i] = X[base + d] + FX[base + d];
        sum += v[i];
    }
#pragma unroll
    for (int o = 16; o > 0; o >>= 1) sum += __shfl_xor_sync(0xffffffffu, sum, o);
    if ((t & 31) == 0) s1[t >> 5] = sum;
    __syncthreads();
    float tot = 0.f;
#pragma unroll
    for (int w = 0; w < 8; w++) tot += s1[w];
    const float mu = tot * (1.0f / 1024.0f);

    float sq = 0.f;
#pragma unroll
    for (int i = 0; i < 4; i++) { float d = v[i] - mu; sq += d * d; }
#pragma unroll
    for (int o = 16; o > 0; o >>= 1) sq += __shfl_xor_sync(0xffffffffu, sq, o);
    if ((t & 31) == 0) s2[t >> 5] = sq;
    __syncthreads();
    float tots = 0.f;
#pragma unroll
    for (int w = 0; w < 8; w++) tots += s2[w];
    const float sd  = sqrtf(tots * (1.0f / 1023.0f));
    const float inv = 1.0f / (sd + 1e-6f);

#pragma unroll
    for (int i = 0; i < 4; i++) {
        const int d = t + i * 256;
        const float val = (v[i] - mu) * inv;
        OUT[base + d] = val;
        __half h, l;
        splitf(val, h, l);
        OH[base + d] = h;
        OL[base + d] = l;
    }
}

// ------------------------- fp16x3 flash attention ----------------------------
constexpr int ATT_K_BYTES  = 128 * 144;
constexpr int ATT_QV_TILE  = 64 * 144;
constexpr int ATT_QV_STAGE = 4 * ATT_QV_TILE;
constexpr int ATT_QV_BASE  = 2 * ATT_K_BYTES;
constexpr int ATT2_SMEM    = ATT_QV_BASE + 2 * ATT_QV_STAGE;

__device__ __forceinline__ void attn_load_qv(
    uint32_t sb, int stage, int j0, int b, int h, int t,
    const __half* __restrict__ Qh, const __half* __restrict__ Ql,
    const __half* __restrict__ Vh, const __half* __restrict__ Vl) {
#pragma unroll
    for (int i = 0; i < 8; i++) {
        int c   = t + i * 256;
        int tp  = c >> 9;
        int row = (c >> 3) & 63;
        int seg = c & 7;
        const __half* base = (tp == 0) ? Qh : (tp == 1) ? Ql
                           : (tp == 2) ? Vh : Vl;
        const __half* src =
            base + ((size_t)(j0 + row) * Bn + b) * QKVN + h * 64 + seg * 8;
        uint32_t dst = sb + ATT_QV_BASE + (uint32_t)stage * ATT_QV_STAGE
                     + tp * ATT_QV_TILE + row * 144 + seg * 16;
        CP16(dst, src);
    }
}

__global__ void __launch_bounds__(256, 1)
attn_mma_kernel(const __half* __restrict__ QKVh, const __half* __restrict__ QKVl,
                float* __restrict__ Ob) {
    extern __shared__ char smem[];
    const uint32_t sb = (uint32_t)__cvta_generic_to_shared(smem);
    const int bh = blockIdx.y, b = bh / Hn, h = bh % Hn;
    const int i0 = blockIdx.x * 128;
    const int t = threadIdx.x, lane = t & 31, wid = t >> 5;

    const __half* Kh = QKVh;
    const __half* Kl = QKVl;
    const __half* Qh = QKVh + 1024;
    const __half* Ql = QKVl + 1024;
    const __half* Vh = QKVh + 2048;
    const __half* Vl = QKVl + 2048;

#pragma unroll
    for (int i = 0; i < 8; i++) {
        int c     = t + i * 256;
        int plane = c >> 10;
        int row   = (c >> 3) & 127;
        int seg   = c & 7;
        const __half* src = (plane ? Kl : Kh)
            + ((size_t)(i0 + row) * Bn + b) * QKVN + h * 64 + seg * 8;
        CP16(sb + plane * ATT_K_BYTES + row * 144 + seg * 16, src);
    }
    CP_COMMIT;
    attn_load_qv(sb, 0, 0, b, h, t, Qh, Ql, Vh, Vl);
    CP_COMMIT;

    CP_WAIT1;
    __syncthreads();

    uint32_t akh[4][4], akl[4][4];
    const uint32_t ka = sb + (uint32_t)((wid * 16 + ((lane >> 3) & 1) * 8 + (lane & 7)) * 144
                                        + (lane >> 4) * 16);
#pragma unroll
    for (int ks = 0; ks < 4; ks++) {
        ldsm4(akh[ks], ka + ks * 32);
        ldsm4(akl[ks], ka + ATT_K_BYTES + ks * 32);
    }

    float m0 = -1e30f, m1 = -1e30f, l0 = 0.f, l1 = 0.f;
    float o[8][4];
#pragma unroll
    for (int n = 0; n < 8; n++)
#pragma unroll
        for (int r = 0; r < 4; r++) o[n][r] = 0.f;

    const uint32_t qoff = (uint32_t)(((lane >> 4) * 8 + (lane & 7)) * 144
                                     + ((lane >> 3) & 1) * 16);
    const uint32_t voff = (uint32_t)((((lane >> 3) & 1) * 8 + (lane & 7)) * 144
                                     + (lane >> 4) * 16);
    const float scl = 0.03125f;

    for (int kt = 0; kt < 16; kt++) {
        if (kt < 15) {
            attn_load_qv(sb, (kt + 1) & 1, (kt + 1) * 64, b, h, t, Qh, Ql, Vh, Vl);
            CP_COMMIT;
            CP_WAIT1;
        } else {
            CP_WAIT0;
        }
        __syncthreads();
        const uint32_t qvb = sb + ATT_QV_BASE + (uint32_t)(kt & 1) * ATT_QV_STAGE;

        float s[8][4];
#pragma unroll
        for (int n = 0; n < 8; n++)
#pragma unroll
            for (int r = 0; r < 4; r++) s[n][r] = 0.f;

#pragma unroll
        for (int ks = 0; ks < 4; ks++) {
#pragma unroll
            for (int np = 0; np < 4; np++) {
                uint32_t qh[4], ql[4];
                const uint32_t qa = qvb + qoff + np * (16 * 144) + ks * 32;
                ldsm4(qh, qa);
                ldsm4(ql, qa + ATT_QV_TILE);
                mma16816(s[2 * np],     akh[ks], qh[0], qh[1]);
                mma16816(s[2 * np + 1], akh[ks], qh[2], qh[3]);
                mma16816(s[2 * np],     akh[ks], ql[0], ql[1]);
                mma16816(s[2 * np + 1], akh[ks], ql[2], ql[3]);
                mma16816(s[2 * np],     akl[ks], qh[0], qh[1]);
                mma16816(s[2 * np + 1], akl[ks], qh[2], qh[3]);
            }
        }

        float mt0 = -1e30f, mt1 = -1e30f;
#pragma unroll
        for (int n = 0; n < 8; n++) {
            s[n][0] *= scl; s[n][1] *= scl; s[n][2] *= scl; s[n][3] *= scl;
            mt0 = fmaxf(mt0, fmaxf(s[n][0], s[n][1]));
            mt1 = fmaxf(mt1, fmaxf(s[n][2], s[n][3]));
        }
        mt0 = fmaxf(mt0, __shfl_xor_sync(0xffffffffu, mt0, 1));
        mt0 = fmaxf(mt0, __shfl_xor_sync(0xffffffffu, mt0, 2));
        mt1 = fmaxf(mt1, __shfl_xor_sync(0xffffffffu, mt1, 1));
        mt1 = fmaxf(mt1, __shfl_xor_sync(0xffffffffu, mt1, 2));
        const float mn0 = fmaxf(m0, mt0), mn1 = fmaxf(m1, mt1);
        const float rs0 = __expf(m0 - mn0), rs1 = __expf(m1 - mn1);
        m0 = mn0; m1 = mn1;

        float ps0 = 0.f, ps1 = 0.f;
#pragma unroll
        for (int n = 0; n < 8; n++) {
            s[n][0] = __expf(s[n][0] - mn0);
            s[n][1] = __expf(s[n][1] - mn0);
            s[n][2] = __expf(s[n][2] - mn1);
            s[n][3] = __expf(s[n][3] - mn1);
            ps0 += s[n][0] + s[n][1];
            ps1 += s[n][2] + s[n][3];
        }
        ps0 += __shfl_xor_sync(0xffffffffu, ps0, 1);
        ps0 += __shfl_xor_sync(0xffffffffu, ps0, 2);
        ps1 += __shfl_xor_sync(0xffffffffu, ps1, 1);
        ps1 += __shfl_xor_sync(0xffffffffu, ps1, 2);
        l0 = l0 * rs0 + ps0;
        l1 = l1 * rs1 + ps1;
#pragma unroll
        for (int n = 0; n < 8; n++) {
            o[n][0] *= rs0; o[n][1] *= rs0;
            o[n][2] *= rs1; o[n][3] *= rs1;
        }

#pragma unroll
        for (int ki = 0; ki < 4; ki++) {
            __half hv[8], lv[8];
            splitf(s[2 * ki][0],     hv[0], lv[0]);
            splitf(s[2 * ki][1],     hv[1], lv[1]);
            splitf(s[2 * ki][2],     hv[2], lv[2]);
            splitf(s[2 * ki][3],     hv[3], lv[3]);
            splitf(s[2 * ki + 1][0], hv[4], lv[4]);
            splitf(s[2 * ki + 1][1], hv[5], lv[5]);
            splitf(s[2 * ki + 1][2], hv[6], lv[6]);
            splitf(s[2 * ki + 1][3], hv[7], lv[7]);
            uint32_t ph[4], pl[4];
            ph[0] = pack2(hv[0], hv[1]); ph[1] = pack2(hv[2], hv[3]);
            ph[2] = pack2(hv[4], hv[5]); ph[3] = pack2(hv[6], hv[7]);
            pl[0] = pack2(lv[0], lv[1]); pl[1] = pack2(lv[2], lv[3]);
            pl[2] = pack2(lv[4], lv[5]); pl[3] = pack2(lv[6], lv[7]);

#pragma unroll
            for (int np = 0; np < 4; np++) {
                uint32_t vh[4], vl[4];
                const uint32_t va = qvb + 2 * ATT_QV_TILE + voff
                                  + ki * (16 * 144) + np * 32;
                ldsm4t(vh, va);
                ldsm4t(vl, va + ATT_QV_TILE);
                mma16816(o[2 * np],     ph, vh[0], vh[1]);
                mma16816(o[2 * np + 1], ph, vh[2], vh[3]);
                mma16816(o[2 * np],     ph, vl[0], vl[1]);
                mma16816(o[2 * np + 1], ph, vl[2], vl[3]);
                mma16816(o[2 * np],     pl, vh[0], vh[1]);
                mma16816(o[2 * np + 1], pl, vh[2], vh[3]);
            }
        }
        __syncthreads();
    }

    const float inv0 = 1.0f / l0, inv1 = 1.0f / l1;
    const int row0 = i0 + wid * 16 + (lane >> 2);
    const int colb = h * 64 + (lane & 3) * 2;
#pragma unroll
    for (int n = 0; n < 8; n++) {
        float2 w0 = {o[n][0] * inv0, o[n][1] * inv0};
        float2 w1 = {o[n][2] * inv1, o[n][3] * inv1};
        *(float2*)(Ob + ((size_t)row0 * Bn + b) * HDQK + colb + n * 8) = w0;
        *(float2*)(Ob + ((size_t)(row0 + 8) * Bn + b) * HDQK + colb + n * 8) = w1;
    }
}

// ------------------------- host driver --------------------------------------
extern "C" void kernel_launch(void* const* d_in, const int* in_sizes, int n_in,
                              void* d_out, int out_size) {
    (void)in_sizes; (void)n_in; (void)out_size;

    const float* x_in = (const float*)d_in[0];
    const float* Wk = (const float*)d_in[2];
    const float* bk = (const float*)d_in[3];
    const float* Wq = (const float*)d_in[4];
    const float* bq = (const float*)d_in[5];
    const float* Wv = (const float*)d_in[6];
    const float* bv = (const float*)d_in[7];
    const float* W1 = (const float*)d_in[8];
    const float* b1 = (const float*)d_in[9];
    const float* W2 = (const float*)d_in[10];
    const float* b2 = (const float*)d_in[11];

    float *px, *pz, *pf, *pa, *pbq;
    cudaGetSymbolAddress((void**)&px, g_x);
    cudaGetSymbolAddress((void**)&pz, g_z);
    cudaGetSymbolAddress((void**)&pf, g_f);
    cudaGetSymbolAddress((void**)&pa, g_att);
    cudaGetSymbolAddress((void**)&pbq, g_bqkv);

    __half *xh, *xl, *zh, *zl, *hh, *hl, *qkh, *qkl;
    __half *wqh, *wql, *w1h, *w1l, *w2h, *w2l;
    cudaGetSymbolAddress((void**)&xh, g_xh);   cudaGetSymbolAddress((void**)&xl, g_xl);
    cudaGetSymbolAddress((void**)&zh, g_zh);   cudaGetSymbolAddress((void**)&zl, g_zl);
    cudaGetSymbolAddress((void**)&hh, g_hh);   cudaGetSymbolAddress((void**)&hl, g_hl);
    cudaGetSymbolAddress((void**)&qkh, g_qkvh); cudaGetSymbolAddress((void**)&qkl, g_qkvl);
    cudaGetSymbolAddress((void**)&wqh, g_wqkvh); cudaGetSymbolAddress((void**)&wql, g_wqkvl);
    cudaGetSymbolAddress((void**)&w1h, g_w1h);   cudaGetSymbolAddress((void**)&w1l, g_w1l);
    cudaGetSymbolAddress((void**)&w2h, g_w2h);   cudaGetSymbolAddress((void**)&w2l, g_w2l);

    cudaFuncSetAttribute(gemm_mma_kernel<1>,
                         cudaFuncAttributeMaxDynamicSharedMemorySize, GEMM_SMEM);
    cudaFuncSetAttribute(gemm_mma_kernel<2>,
                         cudaFuncAttributeMaxDynamicSharedMemorySize, GEMM_SMEM);
    cudaFuncSetAttribute(gemm_mma_kernel<3>,
                         cudaFuncAttributeMaxDynamicSharedMemorySize, GEMM_SMEM);
    cudaFuncSetAttribute(attn_mma_kernel,
                         cudaFuncAttributeMaxDynamicSharedMemorySize, ATT2_SMEM);

    const dim3 blk(256);

    // exactly 5 setup launches so ncu (-s 5 -c 1) captures the first GEMM
    cvt_pair_kernel<<<NTOK * Dn / 1024, blk>>>(x_in, xh, xl, NTOK * Dn / 4);
    cvt_qkv_kernel<<<dim3(Ln * Dn * 1024 / 1024, 3), blk>>>(Wk, Wq, Wv, wqh, wql);
    cvt_pair_kernel<<<Ln * Dn * FFn / 1024, blk>>>(W1, w1h, w1l, Ln * Dn * FFn / 4);
    cvt_pair_kernel<<<Ln * FFn * Dn / 1024, blk>>>(W2, w2h, w2l, Ln * FFn * Dn / 4);
    combine_bias_kernel<<<Ln * QKVN / 256, blk>>>(bk, bq, bv, pbq);

    const dim3 gFF1(FFn / BN, NTOK / BM);    // (32, 32)
    const dim3 gFF2(Dn  / BN, NTOK / BM);    // (8, 32)
    const dim3 gQKV(QKVN / BN, NTOK / BM);   // (24, 32)
    const dim3 gATT(Tn / 128, Bn * Hn);      // (8, 64)

    for (int l = 0; l < Ln; l++) {
        const float* xl32 = (l == 0) ? x_in : px;

        gemm_mma_kernel<1><<<gFF1, blk, GEMM_SMEM>>>(
            xh, xl, w1h + (size_t)l * Dn * FFn, w1l + (size_t)l * Dn * FFn,
            b1 + (size_t)l * FFn, nullptr, hh, hl, NTOK, Dn, FFn);
        gemm_mma_kernel<2><<<gFF2, blk, GEMM_SMEM>>>(
            hh, hl, w2h + (size_t)l * FFn * Dn, w2l + (size_t)l * FFn * Dn,
            b2 + (size_t)l * Dn, pf, nullptr, nullptr, NTOK, FFn, Dn);

        resnorm_kernel<<<NTOK, blk>>>(xl32, pf, pz, zh, zl);

        gemm_mma_kernel<3><<<gQKV, blk, GEMM_SMEM>>>(
            zh, zl, wqh + (size_t)l * Dn * QKVN, wql + (size_t)l * Dn * QKVN,
            pbq + (size_t)l * QKVN, nullptr, qkh, qkl, NTOK, Dn, QKVN);

        attn_mma_kernel<<<gATT, blk, ATT2_SMEM>>>(qkh, qkl, pa);

        float* xout = (l == Ln - 1) ? (float*)d_out : px;
        resnorm_kernel<<<NTOK, blk>>>(pz, pa, xout, xh, xl);
    }
}

// round 7
// speedup vs baseline: 1.6784x; 1.1118x over previous
#include <cuda_runtime.h>
#include <cuda_fp16.h>
#include <math.h>
#include <stdint.h>

// ---------------------------------------------------------------------------
// TinyTransformer on GB300 (sm_103a): fp16x3 mma.sync GEMMs + flash attention.
// T=1024, B=4, D=1024, H=16, DQK=DV=64, FF=4096, L=4.
// tcgen05 unavailable in this harness (PTX target compute_103) -> HMMA path.
// GEMM: 2-stage cp.async early-issue pipeline, 2 CTAs/SM (launch_bounds 256,2)
// to hide ldsm->mma RAW latency and barrier stalls across CTAs.
// ---------------------------------------------------------------------------

constexpr int Tn   = 1024;
constexpr int Bn   = 4;
constexpr int Dn   = 1024;
constexpr int Hn   = 16;
constexpr int FFn  = 4096;
constexpr int Ln   = 4;
constexpr int NTOK = Tn * Bn;       // 4096
constexpr int HDQK = Hn * 64;       // 1024
constexpr int QKVN = 3 * HDQK;      // 3072 fused K|Q|V

// ------------------------- device scratch (no allocs) ----------------------
__device__ float g_x  [NTOK * Dn];
__device__ float g_z  [NTOK * Dn];
__device__ float g_f  [NTOK * Dn];
__device__ float g_att[NTOK * HDQK];

__device__ __half g_xh[NTOK * Dn],  g_xl[NTOK * Dn];
__device__ __half g_zh[NTOK * Dn],  g_zl[NTOK * Dn];
__device__ __half g_hh[NTOK * FFn], g_hl[NTOK * FFn];
__device__ __half g_qkvh[NTOK * QKVN], g_qkvl[NTOK * QKVN];

__device__ __half g_wqkvh[Ln * Dn * QKVN], g_wqkvl[Ln * Dn * QKVN];
__device__ __half g_w1h[Ln * Dn * FFn],  g_w1l[Ln * Dn * FFn];
__device__ __half g_w2h[Ln * FFn * Dn],  g_w2l[Ln * FFn * Dn];
__device__ float g_bqkv[Ln * QKVN];

// ------------------------- PTX helpers -------------------------------------
#define CP16(dst, src) \
    asm volatile("cp.async.cg.shared.global [%0], [%1], 16;" :: "r"(dst), "l"(src))
#define CP_COMMIT asm volatile("cp.async.commit_group;")
#define CP_WAIT1  asm volatile("cp.async.wait_group 1;")
#define CP_WAIT0  asm volatile("cp.async.wait_group 0;")

__device__ __forceinline__ void ldsm4(uint32_t* r, uint32_t a) {
    asm volatile("ldmatrix.sync.aligned.m8n8.x4.shared.b16 {%0,%1,%2,%3}, [%4];"
                 : "=r"(r[0]), "=r"(r[1]), "=r"(r[2]), "=r"(r[3]) : "r"(a));
}
__device__ __forceinline__ void ldsm4t(uint32_t* r, uint32_t a) {
    asm volatile("ldmatrix.sync.aligned.m8n8.x4.trans.shared.b16 {%0,%1,%2,%3}, [%4];"
                 : "=r"(r[0]), "=r"(r[1]), "=r"(r[2]), "=r"(r[3]) : "r"(a));
}
__device__ __forceinline__ void mma16816(float* c, const uint32_t* a,
                                         uint32_t b0, uint32_t b1) {
    asm volatile(
        "mma.sync.aligned.m16n8k16.row.col.f32.f16.f16.f32 "
        "{%0,%1,%2,%3}, {%4,%5,%6,%7}, {%8,%9}, {%0,%1,%2,%3};"
        : "+f"(c[0]), "+f"(c[1]), "+f"(c[2]), "+f"(c[3])
        : "r"(a[0]), "r"(a[1]), "r"(a[2]), "r"(a[3]), "r"(b0), "r"(b1));
}

__device__ __forceinline__ void splitf(float v, __half& h, __half& l) {
    h = __float2half_rn(v);
    l = __float2half_rn(v - __half2float(h));
}
__device__ __forceinline__ uint32_t pack2(__half a, __half b) {
    __half2 v; v.x = a; v.y = b;
    return *(uint32_t*)&v;
}

// ------------------------- fp32 -> split-fp16 reformat -----------------------
__global__ void __launch_bounds__(256)
cvt_pair_kernel(const float* __restrict__ src, __half* __restrict__ hi,
                __half* __restrict__ lo, int n4) {
    int i = blockIdx.x * blockDim.x + threadIdx.x;
    if (i >= n4) return;
    float4 v = ((const float4*)src)[i];
    __half2 h0, h1, l0, l1;
    splitf(v.x, h0.x, l0.x);
    splitf(v.y, h0.y, l0.y);
    splitf(v.z, h1.x, l1.x);
    splitf(v.w, h1.y, l1.y);
    ((__half2*)hi)[i * 2]     = h0;
    ((__half2*)hi)[i * 2 + 1] = h1;
    ((__half2*)lo)[i * 2]     = l0;
    ((__half2*)lo)[i * 2 + 1] = l1;
}

// Wk/Wq/Wv [L][Dn][1024] -> fused planes [L][Dn][3072]
__global__ void __launch_bounds__(256)
cvt_qkv_kernel(const float* __restrict__ Wk, const float* __restrict__ Wq,
               const float* __restrict__ Wv,
               __half* __restrict__ hi, __half* __restrict__ lo) {
    const int tsel = blockIdx.y;
    const float* src = (tsel == 0) ? Wk : (tsel == 1) ? Wq : Wv;
    int i = blockIdx.x * 256 + threadIdx.x;
    float4 v = ((const float4*)src)[i];
    int e  = i * 4;
    int lk = e >> 10;
    int n  = e & 1023;
    size_t o = (size_t)lk * QKVN + (tsel << 10) + n;
    __half2 h0, h1, l0, l1;
    splitf(v.x, h0.x, l0.x);
    splitf(v.y, h0.y, l0.y);
    splitf(v.z, h1.x, l1.x);
    splitf(v.w, h1.y, l1.y);
    *(__half2*)(hi + o)     = h0;
    *(__half2*)(hi + o + 2) = h1;
    *(__half2*)(lo + o)     = l0;
    *(__half2*)(lo + o + 2) = l1;
}

__global__ void __launch_bounds__(256)
combine_bias_kernel(const float* __restrict__ bk, const float* __restrict__ bq,
                    const float* __restrict__ bv, float* __restrict__ out) {
    int i = blockIdx.x * 256 + threadIdx.x;
    int l = i / QKVN, r = i % QKVN;
    float v;
    if (r < 1024)      v = bk[l * 1024 + r];
    else if (r < 2048) v = bq[l * 1024 + r - 1024];
    else               v = bv[l * 1024 + r - 2048];
    out[i] = v;
}

// ------------------------- fp16x3 tensor-core GEMM ---------------------------
// MODE 1: relu + split out.  MODE 2: relu + fp32 out.  MODE 3: split out.
constexpr int BM = 128, BN = 128, BK = 32;
constexpr int ASTR = 80;
constexpr int BSTR = 272;
constexpr int A_BYTES = 128 * ASTR;
constexpr int B_BYTES = 32 * BSTR;
constexpr int STAGE   = 2 * A_BYTES + 2 * B_BYTES;   // 37888
constexpr int GEMM_SMEM = 2 * STAGE;                 // 75776 -> 2 CTAs/SM

template<int MODE>
__global__ void __launch_bounds__(256, 2)
gemm_mma_kernel(const __half* __restrict__ Ah, const __half* __restrict__ Al,
                const __half* __restrict__ Bh, const __half* __restrict__ Bl,
                const float* __restrict__ bias,
                float* __restrict__ Cf,
                __half* __restrict__ Ch, __half* __restrict__ Cl,
                int M, int K, int N) {
    extern __shared__ char smem[];
    const uint32_t sb = (uint32_t)__cvta_generic_to_shared(smem);
    const int t    = threadIdx.x;
    const int row0 = blockIdx.y * BM;
    const int col0 = blockIdx.x * BN;

    const int am = t >> 1, asel = t & 1;
    const int bk = t >> 3, bsel = t & 7;
    const __half* agh = Ah + (size_t)(row0 + am) * K + asel * 16;
    const __half* agl = Al + (size_t)(row0 + am) * K + asel * 16;
    const __half* bgh = Bh + (size_t)bk * N + col0 + bsel * 16;
    const __half* bgl = Bl + (size_t)bk * N + col0 + bsel * 16;
    const uint32_t adst = sb + am * ASTR + asel * 32;
    const uint32_t bdst = sb + 2 * A_BYTES + bk * BSTR + bsel * 32;

#define LOAD_STAGE(kt, s) do {                                                 \
    uint32_t so = (uint32_t)(s) * STAGE;                                       \
    size_t ko  = (size_t)(kt) * BK;                                            \
    size_t kon = ko * N;                                                       \
    CP16(adst + so,                agh + ko);                                  \
    CP16(adst + so + 16,           agh + ko + 8);                              \
    CP16(adst + so + A_BYTES,      agl + ko);                                  \
    CP16(adst + so + A_BYTES + 16, agl + ko + 8);                              \
    CP16(bdst + so,                bgh + kon);                                 \
    CP16(bdst + so + 16,           bgh + kon + 8);                             \
    CP16(bdst + so + B_BYTES,      bgl + kon);                                 \
    CP16(bdst + so + B_BYTES + 16, bgl + kon + 8);                             \
    CP_COMMIT;                                                                 \
} while (0)

    const int lane = t & 31, wid = t >> 5;
    const int wm = wid >> 2, wn = wid & 3;
    const uint32_t afo = (uint32_t)((wm * 64 + ((lane >> 3) & 1) * 8 + (lane & 7)) * ASTR
                                    + (lane >> 4) * 16);
    const uint32_t bfo = (uint32_t)((((lane >> 3) & 1) * 8 + (lane & 7)) * BSTR
                                    + (wn * 32 + (lane >> 4) * 8) * 2);

    float acc[4][4][4];
#pragma unroll
    for (int i = 0; i < 4; i++)
#pragma unroll
        for (int j = 0; j < 4; j++)
#pragma unroll
            for (int r = 0; r < 4; r++) acc[i][j][r] = 0.f;

    const int KT = K / BK;
    LOAD_STAGE(0, 0);

    for (int kt = 0; kt < KT; kt++) {
        // early issue of next stage, then wait for current
        if (kt + 1 < KT) { LOAD_STAGE(kt + 1, (kt + 1) & 1); CP_WAIT1; }
        else             { CP_WAIT0; }
        __syncthreads();

        const uint32_t so   = (uint32_t)(kt & 1) * STAGE;
        const uint32_t ah_b = sb + so + afo;
        const uint32_t al_b = ah_b + A_BYTES;
        const uint32_t bh_b = sb + so + 2 * A_BYTES + bfo;
        const uint32_t bl_b = bh_b + B_BYTES;

#pragma unroll
        for (int ks = 0; ks < 2; ks++) {
            uint32_t ahi[4][4], alo[4][4], bhi[4][2], blo[4][2];
#pragma unroll
            for (int i = 0; i < 4; i++) {
                ldsm4(ahi[i], ah_b + i * (16 * ASTR) + ks * 32);
                ldsm4(alo[i], al_b + i * (16 * ASTR) + ks * 32);
            }
#pragma unroll
            for (int j2 = 0; j2 < 2; j2++) {
                uint32_t r[4];
                ldsm4t(r, bh_b + ks * (16 * BSTR) + j2 * 32);
                bhi[j2 * 2][0] = r[0]; bhi[j2 * 2][1] = r[1];
                bhi[j2 * 2 + 1][0] = r[2]; bhi[j2 * 2 + 1][1] = r[3];
                ldsm4t(r, bl_b + ks * (16 * BSTR) + j2 * 32);
                blo[j2 * 2][0] = r[0]; blo[j2 * 2][1] = r[1];
                blo[j2 * 2 + 1][0] = r[2]; blo[j2 * 2 + 1][1] = r[3];
            }
#pragma unroll
            for (int i = 0; i < 4; i++)
#pragma unroll
                for (int j = 0; j < 4; j++)
                    mma16816(acc[i][j], ahi[i], bhi[j][0], bhi[j][1]);
#pragma unroll
            for (int i = 0; i < 4; i++)
#pragma unroll
                for (int j = 0; j < 4; j++)
                    mma16816(acc[i][j], ahi[i], blo[j][0], blo[j][1]);
#pragma unroll
            for (int i = 0; i < 4; i++)
#pragma unroll
                for (int j = 0; j < 4; j++)
                    mma16816(acc[i][j], alo[i], bhi[j][0], bhi[j][1]);
        }
        __syncthreads();
    }
#undef LOAD_STAGE

    const int rb = row0 + wm * 64 + (lane >> 2);
    const int cb = col0 + wn * 32 + (lane & 3) * 2;
#pragma unroll
    for (int i = 0; i < 4; i++) {
#pragma unroll
        for (int j = 0; j < 4; j++) {
            const int r = rb + i * 16;
            const int c = cb + j * 8;
            const float2 bb = *(const float2*)(bias + c);
            float v0 = acc[i][j][0] + bb.x;
            float v1 = acc[i][j][1] + bb.y;
            float v2 = acc[i][j][2] + bb.x;
            float v3 = acc[i][j][3] + bb.y;
            if (MODE == 1 || MODE == 2) {
                v0 = fmaxf(v0, 0.f); v1 = fmaxf(v1, 0.f);
                v2 = fmaxf(v2, 0.f); v3 = fmaxf(v3, 0.f);
            }
            if (MODE == 1 || MODE == 3) {
                __half2 h, l;
                splitf(v0, h.x, l.x); splitf(v1, h.y, l.y);
                *(__half2*)(Ch + (size_t)r * N + c) = h;
                *(__half2*)(Cl + (size_t)r * N + c) = l;
                splitf(v2, h.x, l.x); splitf(v3, h.y, l.y);
                *(__half2*)(Ch + (size_t)(r + 8) * N + c) = h;
                *(__half2*)(Cl + (size_t)(r + 8) * N + c) = l;
            } else {
                float2 o0 = {v0, v1}, o1 = {v2, v3};
                *(float2*)(Cf + (size_t)r * N + c) = o0;
                *(float2*)(Cf + (size_t)(r + 8) * N + c) = o1;
            }
        }
    }
}

// ------------------------- resnorm ------------------------------------------
__global__ void __launch_bounds__(256)
resnorm_kernel(const float* __restrict__ X, const float* __restrict__ FX,
               float* __restrict__ OUT,
               __half* __restrict__ OH, __half* __restrict__ OL) {
    __shared__ float s1[8];
    __shared__ float s2[8];
    const int row = blockIdx.x;
    const size_t base = (size_t)row * Dn;
    const int t = threadIdx.x;

    float v[4];
    float sum = 0.f;
#pragma unroll
    for (int i = 0; i < 4; i++) {
        int d = t + i * 256;
        v[i] = X[base + d] + FX[base + d];
        sum += v[i];
    }
#pragma unroll
    for (int o = 16; o > 0; o >>= 1) sum += __shfl_xor_sync(0xffffffffu, sum, o);
    if ((t & 31) == 0) s1[t >> 5] = sum;
    __syncthreads();
    float tot = 0.f;
#pragma unroll
    for (int w = 0; w < 8; w++) tot += s1[w];
    const float mu = tot * (1.0f / 1024.0f);

    float sq = 0.f;
#pragma unroll
    for (int i = 0; i < 4; i++) { float d = v[i] - mu; sq += d * d; }
#pragma unroll
    for (int o = 16; o > 0; o >>= 1) sq += __shfl_xor_sync(0xffffffffu, sq, o);
    if ((t & 31) == 0) s2[t >> 5] = sq;
    __syncthreads();
    float tots = 0.f;
#pragma unroll
    for (int w = 0; w < 8; w++) tots += s2[w];
    const float sd  = sqrtf(tots * (1.0f / 1023.0f));
    const float inv = 1.0f / (sd + 1e-6f);

#pragma unroll
    for (int i = 0; i < 4; i++) {
        const int d = t + i * 256;
        const float val = (v[i] - mu) * inv;
        OUT[base + d] = val;
        __half h, l;
        splitf(val, h, l);
        OH[base + d] = h;
        OL[base + d] = l;
    }
}

// ------------------------- fp16x3 flash attention ----------------------------
constexpr int ATT_K_BYTES  = 128 * 144;
constexpr int ATT_QV_TILE  = 64 * 144;
constexpr int ATT_QV_STAGE = 4 * ATT_QV_TILE;
constexpr int ATT_QV_BASE  = 2 * ATT_K_BYTES;
constexpr int ATT2_SMEM    = ATT_QV_BASE + 2 * ATT_QV_STAGE;

__device__ __forceinline__ void attn_load_qv(
    uint32_t sb, int stage, int j0, int b, int h, int t,
    const __half* __restrict__ Qh, const __half* __restrict__ Ql,
    const __half* __restrict__ Vh, const __half* __restrict__ Vl) {
#pragma unroll
    for (int i = 0; i < 8; i++) {
        int c   = t + i * 256;
        int tp  = c >> 9;
        int row = (c >> 3) & 63;
        int seg = c & 7;
        const __half* base = (tp == 0) ? Qh : (tp == 1) ? Ql
                           : (tp == 2) ? Vh : Vl;
        const __half* src =
            base + ((size_t)(j0 + row) * Bn + b) * QKVN + h * 64 + seg * 8;
        uint32_t dst = sb + ATT_QV_BASE + (uint32_t)stage * ATT_QV_STAGE
                     + tp * ATT_QV_TILE + row * 144 + seg * 16;
        CP16(dst, src);
    }
}

__global__ void __launch_bounds__(256, 1)
attn_mma_kernel(const __half* __restrict__ QKVh, const __half* __restrict__ QKVl,
                float* __restrict__ Ob) {
    extern __shared__ char smem[];
    const uint32_t sb = (uint32_t)__cvta_generic_to_shared(smem);
    const int bh = blockIdx.y, b = bh / Hn, h = bh % Hn;
    const int i0 = blockIdx.x * 128;
    const int t = threadIdx.x, lane = t & 31, wid = t >> 5;

    const __half* Kh = QKVh;
    const __half* Kl = QKVl;
    const __half* Qh = QKVh + 1024;
    const __half* Ql = QKVl + 1024;
    const __half* Vh = QKVh + 2048;
    const __half* Vl = QKVl + 2048;

#pragma unroll
    for (int i = 0; i < 8; i++) {
        int c     = t + i * 256;
        int plane = c >> 10;
        int row   = (c >> 3) & 127;
        int seg   = c & 7;
        const __half* src = (plane ? Kl : Kh)
            + ((size_t)(i0 + row) * Bn + b) * QKVN + h * 64 + seg * 8;
        CP16(sb + plane * ATT_K_BYTES + row * 144 + seg * 16, src);
    }
    CP_COMMIT;
    attn_load_qv(sb, 0, 0, b, h, t, Qh, Ql, Vh, Vl);
    CP_COMMIT;

    CP_WAIT1;
    __syncthreads();

    uint32_t akh[4][4], akl[4][4];
    const uint32_t ka = sb + (uint32_t)((wid * 16 + ((lane >> 3) & 1) * 8 + (lane & 7)) * 144
                                        + (lane >> 4) * 16);
#pragma unroll
    for (int ks = 0; ks < 4; ks++) {
        ldsm4(akh[ks], ka + ks * 32);
        ldsm4(akl[ks], ka + ATT_K_BYTES + ks * 32);
    }

    float m0 = -1e30f, m1 = -1e30f, l0 = 0.f, l1 = 0.f;
    float o[8][4];
#pragma unroll
    for (int n = 0; n < 8; n++)
#pragma unroll
        for (int r = 0; r < 4; r++) o[n][r] = 0.f;

    const uint32_t qoff = (uint32_t)(((lane >> 4) * 8 + (lane & 7)) * 144
                                     + ((lane >> 3) & 1) * 16);
    const uint32_t voff = (uint32_t)((((lane >> 3) & 1) * 8 + (lane & 7)) * 144
                                     + (lane >> 4) * 16);
    const float scl = 0.03125f;

    for (int kt = 0; kt < 16; kt++) {
        if (kt < 15) {
            attn_load_qv(sb, (kt + 1) & 1, (kt + 1) * 64, b, h, t, Qh, Ql, Vh, Vl);
            CP_COMMIT;
            CP_WAIT1;
        } else {
            CP_WAIT0;
        }
        __syncthreads();
        const uint32_t qvb = sb + ATT_QV_BASE + (uint32_t)(kt & 1) * ATT_QV_STAGE;

        float s[8][4];
#pragma unroll
        for (int n = 0; n < 8; n++)
#pragma unroll
            for (int r = 0; r < 4; r++) s[n][r] = 0.f;

#pragma unroll
        for (int ks = 0; ks < 4; ks++) {
#pragma unroll
            for (int np = 0; np < 4; np++) {
                uint32_t qh[4], ql[4];
                const uint32_t qa = qvb + qoff + np * (16 * 144) + ks * 32;
                ldsm4(qh, qa);
                ldsm4(ql, qa + ATT_QV_TILE);
                mma16816(s[2 * np],     akh[ks], qh[0], qh[1]);
                mma16816(s[2 * np + 1], akh[ks], qh[2], qh[3]);
                mma16816(s[2 * np],     akh[ks], ql[0], ql[1]);
                mma16816(s[2 * np + 1], akh[ks], ql[2], ql[3]);
                mma16816(s[2 * np],     akl[ks], qh[0], qh[1]);
                mma16816(s[2 * np + 1], akl[ks], qh[2], qh[3]);
            }
        }

        float mt0 = -1e30f, mt1 = -1e30f;
#pragma unroll
        for (int n = 0; n < 8; n++) {
            s[n][0] *= scl; s[n][1] *= scl; s[n][2] *= scl; s[n][3] *= scl;
            mt0 = fmaxf(mt0, fmaxf(s[n][0], s[n][1]));
            mt1 = fmaxf(mt1, fmaxf(s[n][2], s[n][3]));
        }
        mt0 = fmaxf(mt0, __shfl_xor_sync(0xffffffffu, mt0, 1));
        mt0 = fmaxf(mt0, __shfl_xor_sync(0xffffffffu, mt0, 2));
        mt1 = fmaxf(mt1, __shfl_xor_sync(0xffffffffu, mt1, 1));
        mt1 = fmaxf(mt1, __shfl_xor_sync(0xffffffffu, mt1, 2));
        const float mn0 = fmaxf(m0, mt0), mn1 = fmaxf(m1, mt1);
        const float rs0 = __expf(m0 - mn0), rs1 = __expf(m1 - mn1);
        m0 = mn0; m1 = mn1;

        float ps0 = 0.f, ps1 = 0.f;
#pragma unroll
        for (int n = 0; n < 8; n++) {
            s[n][0] = __expf(s[n][0] - mn0);
            s[n][1] = __expf(s[n][1] - mn0);
            s[n][2] = __expf(s[n][2] - mn1);
            s[n][3] = __expf(s[n][3] - mn1);
            ps0 += s[n][0] + s[n][1];
            ps1 += s[n][2] + s[n][3];
        }
        ps0 += __shfl_xor_sync(0xffffffffu, ps0, 1);
        ps0 += __shfl_xor_sync(0xffffffffu, ps0, 2);
        ps1 += __shfl_xor_sync(0xffffffffu, ps1, 1);
        ps1 += __shfl_xor_sync(0xffffffffu, ps1, 2);
        l0 = l0 * rs0 + ps0;
        l1 = l1 * rs1 + ps1;
#pragma unroll
        for (int n = 0; n < 8; n++) {
            o[n][0] *= rs0; o[n][1] *= rs0;
            o[n][2] *= rs1; o[n][3] *= rs1;
        }

#pragma unroll
        for (int ki = 0; ki < 4; ki++) {
            __half hv[8], lv[8];
            splitf(s[2 * ki][0],     hv[0], lv[0]);
            splitf(s[2 * ki][1],     hv[1], lv[1]);
            splitf(s[2 * ki][2],     hv[2], lv[2]);
            splitf(s[2 * ki][3],     hv[3], lv[3]);
            splitf(s[2 * ki + 1][0], hv[4], lv[4]);
            splitf(s[2 * ki + 1][1], hv[5], lv[5]);
            splitf(s[2 * ki + 1][2], hv[6], lv[6]);
            splitf(s[2 * ki + 1][3], hv[7], lv[7]);
            uint32_t ph[4], pl[4];
            ph[0] = pack2(hv[0], hv[1]); ph[1] = pack2(hv[2], hv[3]);
            ph[2] = pack2(hv[4], hv[5]); ph[3] = pack2(hv[6], hv[7]);
            pl[0] = pack2(lv[0], lv[1]); pl[1] = pack2(lv[2], lv[3]);
            pl[2] = pack2(lv[4], lv[5]); pl[3] = pack2(lv[6], lv[7]);

#pragma unroll
            for (int np = 0; np < 4; np++) {
                uint32_t vh[4], vl[4];
                const uint32_t va = qvb + 2 * ATT_QV_TILE + voff
                                  + ki * (16 * 144) + np * 32;
                ldsm4t(vh, va);
                ldsm4t(vl, va + ATT_QV_TILE);
                mma16816(o[2 * np],     ph, vh[0], vh[1]);
                mma16816(o[2 * np + 1], ph, vh[2], vh[3]);
                mma16816(o[2 * np],     ph, vl[0], vl[1]);
                mma16816(o[2 * np + 1], ph, vl[2], vl[3]);
                mma16816(o[2 * np],     pl, vh[0], vh[1]);
                mma16816(o[2 * np + 1], pl, vh[2], vh[3]);
            }
        }
        __syncthreads();
    }

    const float inv0 = 1.0f / l0, inv1 = 1.0f / l1;
    const int row0 = i0 + wid * 16 + (lane >> 2);
    const int colb = h * 64 + (lane & 3) * 2;
#pragma unroll
    for (int n = 0; n < 8; n++) {
        float2 w0 = {o[n][0] * inv0, o[n][1] * inv0};
        float2 w1 = {o[n][2] * inv1, o[n][3] * inv1};
        *(float2*)(Ob + ((size_t)row0 * Bn + b) * HDQK + colb + n * 8) = w0;
        *(float2*)(Ob + ((size_t)(row0 + 8) * Bn + b) * HDQK + colb + n * 8) = w1;
    }
}

// ------------------------- host driver --------------------------------------
extern "C" void kernel_launch(void* const* d_in, const int* in_sizes, int n_in,
                              void* d_out, int out_size) {
    (void)in_sizes; (void)n_in; (void)out_size;

    const float* x_in = (const float*)d_in[0];
    const float* Wk = (const float*)d_in[2];
    const float* bk = (const float*)d_in[3];
    const float* Wq = (const float*)d_in[4];
    const float* bq = (const float*)d_in[5];
    const float* Wv = (const float*)d_in[6];
    const float* bv = (const float*)d_in[7];
    const float* W1 = (const float*)d_in[8];
    const float* b1 = (const float*)d_in[9];
    const float* W2 = (const float*)d_in[10];
    const float* b2 = (const float*)d_in[11];

    float *px, *pz, *pf, *pa, *pbq;
    cudaGetSymbolAddress((void**)&px, g_x);
    cudaGetSymbolAddress((void**)&pz, g_z);
    cudaGetSymbolAddress((void**)&pf, g_f);
    cudaGetSymbolAddress((void**)&pa, g_att);
    cudaGetSymbolAddress((void**)&pbq, g_bqkv);

    __half *xh, *xl, *zh, *zl, *hh, *hl, *qkh, *qkl;
    __half *wqh, *wql, *w1h, *w1l, *w2h, *w2l;
    cudaGetSymbolAddress((void**)&xh, g_xh);   cudaGetSymbolAddress((void**)&xl, g_xl);
    cudaGetSymbolAddress((void**)&zh, g_zh);   cudaGetSymbolAddress((void**)&zl, g_zl);
    cudaGetSymbolAddress((void**)&hh, g_hh);   cudaGetSymbolAddress((void**)&hl, g_hl);
    cudaGetSymbolAddress((void**)&qkh, g_qkvh); cudaGetSymbolAddress((void**)&qkl, g_qkvl);
    cudaGetSymbolAddress((void**)&wqh, g_wqkvh); cudaGetSymbolAddress((void**)&wql, g_wqkvl);
    cudaGetSymbolAddress((void**)&w1h, g_w1h);   cudaGetSymbolAddress((void**)&w1l, g_w1l);
    cudaGetSymbolAddress((void**)&w2h, g_w2h);   cudaGetSymbolAddress((void**)&w2l, g_w2l);

    cudaFuncSetAttribute(gemm_mma_kernel<1>,
                         cudaFuncAttributeMaxDynamicSharedMemorySize, GEMM_SMEM);
    cudaFuncSetAttribute(gemm_mma_kernel<2>,
                         cudaFuncAttributeMaxDynamicSharedMemorySize, GEMM_SMEM);
    cudaFuncSetAttribute(gemm_mma_kernel<3>,
                         cudaFuncAttributeMaxDynamicSharedMemorySize, GEMM_SMEM);
    cudaFuncSetAttribute(attn_mma_kernel,
                         cudaFuncAttributeMaxDynamicSharedMemorySize, ATT2_SMEM);

    const dim3 blk(256);

    // exactly 5 setup launches so ncu lands on a GEMM
    cvt_pair_kernel<<<NTOK * Dn / 1024, blk>>>(x_in, xh, xl, NTOK * Dn / 4);
    cvt_qkv_kernel<<<dim3(Ln * Dn * 1024 / 1024, 3), blk>>>(Wk, Wq, Wv, wqh, wql);
    cvt_pair_kernel<<<Ln * Dn * FFn / 1024, blk>>>(W1, w1h, w1l, Ln * Dn * FFn / 4);
    cvt_pair_kernel<<<Ln * FFn * Dn / 1024, blk>>>(W2, w2h, w2l, Ln * FFn * Dn / 4);
    combine_bias_kernel<<<Ln * QKVN / 256, blk>>>(bk, bq, bv, pbq);

    const dim3 gFF1(FFn / BN, NTOK / BM);    // (32, 32)
    const dim3 gFF2(Dn  / BN, NTOK / BM);    // (8, 32)
    const dim3 gQKV(QKVN / BN, NTOK / BM);   // (24, 32)
    const dim3 gATT(Tn / 128, Bn * Hn);      // (8, 64)

    for (int l = 0; l < Ln; l++) {
        const float* xl32 = (l == 0) ? x_in : px;

        gemm_mma_kernel<1><<<gFF1, blk, GEMM_SMEM>>>(
            xh, xl, w1h + (size_t)l * Dn * FFn, w1l + (size_t)l * Dn * FFn,
            b1 + (size_t)l * FFn, nullptr, hh, hl, NTOK, Dn, FFn);
        gemm_mma_kernel<2><<<gFF2, blk, GEMM_SMEM>>>(
            hh, hl, w2h + (size_t)l * FFn * Dn, w2l + (size_t)l * FFn * Dn,
            b2 + (size_t)l * Dn, pf, nullptr, nullptr, NTOK, FFn, Dn);

        resnorm_kernel<<<NTOK, blk>>>(xl32, pf, pz, zh, zl);

        gemm_mma_kernel<3><<<gQKV, blk, GEMM_SMEM>>>(
            zh, zl, wqh + (size_t)l * Dn * QKVN, wql + (size_t)l * Dn * QKVN,
            pbq + (size_t)l * QKVN, nullptr, qkh, qkl, NTOK, Dn, QKVN);

        attn_mma_kernel<<<gATT, blk, ATT2_SMEM>>>(qkh, qkl, pa);

        float* xout = (l == Ln - 1) ? (float*)d_out : px;
        resnorm_kernel<<<NTOK, blk>>>(pz, pa, xout, xh, xl);
    }
}

// round 9
// speedup vs baseline: 2.2818x; 1.3595x over previous
#include <cuda_runtime.h>
#include <cuda_fp16.h>
#include <math.h>
#include <stdint.h>

// ---------------------------------------------------------------------------
// TinyTransformer on GB300 (sm_103a): 2-term fp16 mma.sync GEMMs (A single
// plane, W split hi/lo) + 3-term fp16x3 flash attention.
// HMMA ceiling ~344 TF/s is the binding constraint -> cut MMA count 3->2.
// (Resubmission of round-7 kernel: round-8 bench was an infra failure.)
// ---------------------------------------------------------------------------

constexpr int Tn   = 1024;
constexpr int Bn   = 4;
constexpr int Dn   = 1024;
constexpr int Hn   = 16;
constexpr int FFn  = 4096;
constexpr int Ln   = 4;
constexpr int NTOK = Tn * Bn;       // 4096
constexpr int HDQK = Hn * 64;       // 1024
constexpr int QKVN = 3 * HDQK;      // 3072 fused K|Q|V

// ------------------------- device scratch (no allocs) ----------------------
__device__ float g_x  [NTOK * Dn];
__device__ float g_z  [NTOK * Dn];
__device__ float g_f  [NTOK * Dn];
__device__ float g_att[NTOK * HDQK];

__device__ __half g_xh[NTOK * Dn];
__device__ __half g_zh[NTOK * Dn];
__device__ __half g_hh[NTOK * FFn];
__device__ __half g_qkvh[NTOK * QKVN], g_qkvl[NTOK * QKVN];

__device__ __half g_wqkvh[Ln * Dn * QKVN], g_wqkvl[Ln * Dn * QKVN];
__device__ __half g_w1h[Ln * Dn * FFn],  g_w1l[Ln * Dn * FFn];
__device__ __half g_w2h[Ln * FFn * Dn],  g_w2l[Ln * FFn * Dn];
__device__ float g_bqkv[Ln * QKVN];

// ------------------------- PTX helpers -------------------------------------
#define CP16(dst, src) \
    asm volatile("cp.async.cg.shared.global [%0], [%1], 16;" :: "r"(dst), "l"(src))
#define CP_COMMIT asm volatile("cp.async.commit_group;")
#define CP_WAIT1  asm volatile("cp.async.wait_group 1;")
#define CP_WAIT0  asm volatile("cp.async.wait_group 0;")

__device__ __forceinline__ void ldsm4(uint32_t* r, uint32_t a) {
    asm volatile("ldmatrix.sync.aligned.m8n8.x4.shared.b16 {%0,%1,%2,%3}, [%4];"
                 : "=r"(r[0]), "=r"(r[1]), "=r"(r[2]), "=r"(r[3]) : "r"(a));
}
__device__ __forceinline__ void ldsm4t(uint32_t* r, uint32_t a) {
    asm volatile("ldmatrix.sync.aligned.m8n8.x4.trans.shared.b16 {%0,%1,%2,%3}, [%4];"
                 : "=r"(r[0]), "=r"(r[1]), "=r"(r[2]), "=r"(r[3]) : "r"(a));
}
__device__ __forceinline__ void mma16816(float* c, const uint32_t* a,
                                         uint32_t b0, uint32_t b1) {
    asm volatile(
        "mma.sync.aligned.m16n8k16.row.col.f32.f16.f16.f32 "
        "{%0,%1,%2,%3}, {%4,%5,%6,%7}, {%8,%9}, {%0,%1,%2,%3};"
        : "+f"(c[0]), "+f"(c[1]), "+f"(c[2]), "+f"(c[3])
        : "r"(a[0]), "r"(a[1]), "r"(a[2]), "r"(a[3]), "r"(b0), "r"(b1));
}

__device__ __forceinline__ void splitf(float v, __half& h, __half& l) {
    h = __float2half_rn(v);
    l = __float2half_rn(v - __half2float(h));
}
__device__ __forceinline__ uint32_t pack2(__half a, __half b) {
    __half2 v; v.x = a; v.y = b;
    return *(uint32_t*)&v;
}

// ------------------------- fp32 -> fp16 reformats ----------------------------
__global__ void __launch_bounds__(256)
cvt1_kernel(const float* __restrict__ src, __half* __restrict__ dst, int n4) {
    int i = blockIdx.x * blockDim.x + threadIdx.x;
    if (i >= n4) return;
    float4 v = ((const float4*)src)[i];
    __half2 h0, h1;
    h0.x = __float2half_rn(v.x); h0.y = __float2half_rn(v.y);
    h1.x = __float2half_rn(v.z); h1.y = __float2half_rn(v.w);
    ((__half2*)dst)[i * 2]     = h0;
    ((__half2*)dst)[i * 2 + 1] = h1;
}

__global__ void __launch_bounds__(256)
cvt_pair_kernel(const float* __restrict__ src, __half* __restrict__ hi,
                __half* __restrict__ lo, int n4) {
    int i = blockIdx.x * blockDim.x + threadIdx.x;
    if (i >= n4) return;
    float4 v = ((const float4*)src)[i];
    __half2 h0, h1, l0, l1;
    splitf(v.x, h0.x, l0.x);
    splitf(v.y, h0.y, l0.y);
    splitf(v.z, h1.x, l1.x);
    splitf(v.w, h1.y, l1.y);
    ((__half2*)hi)[i * 2]     = h0;
    ((__half2*)hi)[i * 2 + 1] = h1;
    ((__half2*)lo)[i * 2]     = l0;
    ((__half2*)lo)[i * 2 + 1] = l1;
}

// Wk/Wq/Wv [L][Dn][1024] -> fused split planes [L][Dn][3072]
__global__ void __launch_bounds__(256)
cvt_qkv_kernel(const float* __restrict__ Wk, const float* __restrict__ Wq,
               const float* __restrict__ Wv,
               __half* __restrict__ hi, __half* __restrict__ lo) {
    const int tsel = blockIdx.y;
    const float* src = (tsel == 0) ? Wk : (tsel == 1) ? Wq : Wv;
    int i = blockIdx.x * 256 + threadIdx.x;
    float4 v = ((const float4*)src)[i];
    int e  = i * 4;
    int lk = e >> 10;
    int n  = e & 1023;
    size_t o = (size_t)lk * QKVN + (tsel << 10) + n;
    __half2 h0, h1, l0, l1;
    splitf(v.x, h0.x, l0.x);
    splitf(v.y, h0.y, l0.y);
    splitf(v.z, h1.x, l1.x);
    splitf(v.w, h1.y, l1.y);
    *(__half2*)(hi + o)     = h0;
    *(__half2*)(hi + o + 2) = h1;
    *(__half2*)(lo + o)     = l0;
    *(__half2*)(lo + o + 2) = l1;
}

__global__ void __launch_bounds__(256)
combine_bias_kernel(const float* __restrict__ bk, const float* __restrict__ bq,
                    const float* __restrict__ bv, float* __restrict__ out) {
    int i = blockIdx.x * 256 + threadIdx.x;
    int l = i / QKVN, r = i % QKVN;
    float v;
    if (r < 1024)      v = bk[l * 1024 + r];
    else if (r < 2048) v = bq[l * 1024 + r - 1024];
    else               v = bv[l * 1024 + r - 2048];
    out[i] = v;
}

// ------------------------- 2-term fp16 tensor-core GEMM ----------------------
// C = A(fp16) @ (Wh + Wl) + bias.  2 MMAs per tile instead of 3.
// MODE 1: relu + fp16 out.  MODE 2: relu + fp32 out.  MODE 3: split-pair out.
constexpr int BM = 128, BN = 128, BK = 32;
constexpr int ASTR = 80;
constexpr int BSTR = 272;
constexpr int A_BYTES = 128 * ASTR;                 // 10240 (single plane)
constexpr int B_BYTES = 32 * BSTR;                  // 8704 per plane
constexpr int STAGE   = A_BYTES + 2 * B_BYTES;      // 27648
constexpr int GEMM_SMEM = 2 * STAGE;                // 55296 -> 2 CTAs/SM

template<int MODE>
__global__ void __launch_bounds__(256, 2)
gemm_mma_kernel(const __half* __restrict__ Ah,
                const __half* __restrict__ Bh, const __half* __restrict__ Bl,
                const float* __restrict__ bias,
                float* __restrict__ Cf,
                __half* __restrict__ Ch, __half* __restrict__ Cl,
                int M, int K, int N) {
    extern __shared__ char smem[];
    const uint32_t sb = (uint32_t)__cvta_generic_to_shared(smem);
    const int t    = threadIdx.x;
    const int row0 = blockIdx.y * BM;
    const int col0 = blockIdx.x * BN;

    const int am = t >> 1, asel = t & 1;
    const int bk = t >> 3, bsel = t & 7;
    const __half* agh = Ah + (size_t)(row0 + am) * K + asel * 16;
    const __half* bgh = Bh + (size_t)bk * N + col0 + bsel * 16;
    const __half* bgl = Bl + (size_t)bk * N + col0 + bsel * 16;
    const uint32_t adst = sb + am * ASTR + asel * 32;
    const uint32_t bdst = sb + A_BYTES + bk * BSTR + bsel * 32;

#define LOAD_STAGE(kt, s) do {                                                 \
    uint32_t so = (uint32_t)(s) * STAGE;                                       \
    size_t ko  = (size_t)(kt) * BK;                                            \
    size_t kon = ko * N;                                                       \
    CP16(adst + so,                agh + ko);                                  \
    CP16(adst + so + 16,           agh + ko + 8);                              \
    CP16(bdst + so,                bgh + kon);                                 \
    CP16(bdst + so + 16,           bgh + kon + 8);                             \
    CP16(bdst + so + B_BYTES,      bgl + kon);                                 \
    CP16(bdst + so + B_BYTES + 16, bgl + kon + 8);                             \
    CP_COMMIT;                                                                 \
} while (0)

    const int lane = t & 31, wid = t >> 5;
    const int wm = wid >> 2, wn = wid & 3;
    const uint32_t afo = (uint32_t)((wm * 64 + ((lane >> 3) & 1) * 8 + (lane & 7)) * ASTR
                                    + (lane >> 4) * 16);
    const uint32_t bfo = (uint32_t)((((lane >> 3) & 1) * 8 + (lane & 7)) * BSTR
                                    + (wn * 32 + (lane >> 4) * 8) * 2);

    float acc[4][4][4];
#pragma unroll
    for (int i = 0; i < 4; i++)
#pragma unroll
        for (int j = 0; j < 4; j++)
#pragma unroll
            for (int r = 0; r < 4; r++) acc[i][j][r] = 0.f;

    const int KT = K / BK;
    LOAD_STAGE(0, 0);

    for (int kt = 0; kt < KT; kt++) {
        if (kt + 1 < KT) { LOAD_STAGE(kt + 1, (kt + 1) & 1); CP_WAIT1; }
        else             { CP_WAIT0; }
        __syncthreads();

        const uint32_t so   = (uint32_t)(kt & 1) * STAGE;
        const uint32_t ah_b = sb + so + afo;
        const uint32_t bh_b = sb + so + A_BYTES + bfo;
        const uint32_t bl_b = bh_b + B_BYTES;

#pragma unroll
        for (int ks = 0; ks < 2; ks++) {
            uint32_t ahi[4][4], bhi[4][2], blo[4][2];
#pragma unroll
            for (int i = 0; i < 4; i++)
                ldsm4(ahi[i], ah_b + i * (16 * ASTR) + ks * 32);
#pragma unroll
            for (int j2 = 0; j2 < 2; j2++) {
                uint32_t r[4];
                ldsm4t(r, bh_b + ks * (16 * BSTR) + j2 * 32);
                bhi[j2 * 2][0] = r[0]; bhi[j2 * 2][1] = r[1];
                bhi[j2 * 2 + 1][0] = r[2]; bhi[j2 * 2 + 1][1] = r[3];
                ldsm4t(r, bl_b + ks * (16 * BSTR) + j2 * 32);
                blo[j2 * 2][0] = r[0]; blo[j2 * 2][1] = r[1];
                blo[j2 * 2 + 1][0] = r[2]; blo[j2 * 2 + 1][1] = r[3];
            }
#pragma unroll
            for (int i = 0; i < 4; i++)
#pragma unroll
                for (int j = 0; j < 4; j++)
                    mma16816(acc[i][j], ahi[i], bhi[j][0], bhi[j][1]);
#pragma unroll
            for (int i = 0; i < 4; i++)
#pragma unroll
                for (int j = 0; j < 4; j++)
                    mma16816(acc[i][j], ahi[i], blo[j][0], blo[j][1]);
        }
        __syncthreads();
    }
#undef LOAD_STAGE

    const int rb = row0 + wm * 64 + (lane >> 2);
    const int cb = col0 + wn * 32 + (lane & 3) * 2;
#pragma unroll
    for (int i = 0; i < 4; i++) {
#pragma unroll
        for (int j = 0; j < 4; j++) {
            const int r = rb + i * 16;
            const int c = cb + j * 8;
            const float2 bb = *(const float2*)(bias + c);
            float v0 = acc[i][j][0] + bb.x;
            float v1 = acc[i][j][1] + bb.y;
            float v2 = acc[i][j][2] + bb.x;
            float v3 = acc[i][j][3] + bb.y;
            if (MODE == 1 || MODE == 2) {
                v0 = fmaxf(v0, 0.f); v1 = fmaxf(v1, 0.f);
                v2 = fmaxf(v2, 0.f); v3 = fmaxf(v3, 0.f);
            }
            if (MODE == 1) {
                __half2 h;
                h.x = __float2half_rn(v0); h.y = __float2half_rn(v1);
                *(__half2*)(Ch + (size_t)r * N + c) = h;
                h.x = __float2half_rn(v2); h.y = __float2half_rn(v3);
                *(__half2*)(Ch + (size_t)(r + 8) * N + c) = h;
            } else if (MODE == 3) {
                __half2 h, l;
                splitf(v0, h.x, l.x); splitf(v1, h.y, l.y);
                *(__half2*)(Ch + (size_t)r * N + c) = h;
                *(__half2*)(Cl + (size_t)r * N + c) = l;
                splitf(v2, h.x, l.x); splitf(v3, h.y, l.y);
                *(__half2*)(Ch + (size_t)(r + 8) * N + c) = h;
                *(__half2*)(Cl + (size_t)(r + 8) * N + c) = l;
            } else {
                float2 o0 = {v0, v1}, o1 = {v2, v3};
                *(float2*)(Cf + (size_t)r * N + c) = o0;
                *(float2*)(Cf + (size_t)(r + 8) * N + c) = o1;
            }
        }
    }
}

// ------------------------- resnorm ------------------------------------------
__global__ void __launch_bounds__(256)
resnorm_kernel(const float* __restrict__ X, const float* __restrict__ FX,
               float* __restrict__ OUT, __half* __restrict__ OH) {
    __shared__ float s1[8];
    __shared__ float s2[8];
    const int row = blockIdx.x;
    const size_t base = (size_t)row * Dn;
    const int t = threadIdx.x;

    float v[4];
    float sum = 0.f;
#pragma unroll
    for (int i = 0; i < 4; i++) {
        int d = t + i * 256;
        v[i] = X[base + d] + FX[base + d];
        sum += v[i];
    }
#pragma unroll
    for (int o = 16; o > 0; o >>= 1) sum += __shfl_xor_sync(0xffffffffu, sum, o);
    if ((t & 31) == 0) s1[t >> 5] = sum;
    __syncthreads();
    float tot = 0.f;
#pragma unroll
    for (int w = 0; w < 8; w++) tot += s1[w];
    const float mu = tot * (1.0f / 1024.0f);

    float sq = 0.f;
#pragma unroll
    for (int i = 0; i < 4; i++) { float d = v[i] - mu; sq += d * d; }
#pragma unroll
    for (int o = 16; o > 0; o >>= 1) sq += __shfl_xor_sync(0xffffffffu, sq, o);
    if ((t & 31) == 0) s2[t >> 5] = sq;
    __syncthreads();
    float tots = 0.f;
#pragma unroll
    for (int w = 0; w < 8; w++) tots += s2[w];
    const float sd  = sqrtf(tots * (1.0f / 1023.0f));
    const float inv = 1.0f / (sd + 1e-6f);

#pragma unroll
    for (int i = 0; i < 4; i++) {
        const int d = t + i * 256;
        const float val = (v[i] - mu) * inv;
        OUT[base + d] = val;
        OH[base + d]  = __float2half_rn(val);
    }
}

// ------------------------- fp16x3 flash attention (3-term) -------------------
constexpr int ATT_K_BYTES  = 128 * 144;
constexpr int ATT_QV_TILE  = 64 * 144;
constexpr int ATT_QV_STAGE = 4 * ATT_QV_TILE;
constexpr int ATT_QV_BASE  = 2 * ATT_K_BYTES;
constexpr int ATT2_SMEM    = ATT_QV_BASE + 2 * ATT_QV_STAGE;

__device__ __forceinline__ void attn_load_qv(
    uint32_t sb, int stage, int j0, int b, int h, int t,
    const __half* __restrict__ Qh, const __half* __restrict__ Ql,
    const __half* __restrict__ Vh, const __half* __restrict__ Vl) {
#pragma unroll
    for (int i = 0; i < 8; i++) {
        int c   = t + i * 256;
        int tp  = c >> 9;
        int row = (c >> 3) & 63;
        int seg = c & 7;
        const __half* base = (tp == 0) ? Qh : (tp == 1) ? Ql
                           : (tp == 2) ? Vh : Vl;
        const __half* src =
            base + ((size_t)(j0 + row) * Bn + b) * QKVN + h * 64 + seg * 8;
        uint32_t dst = sb + ATT_QV_BASE + (uint32_t)stage * ATT_QV_STAGE
                     + tp * ATT_QV_TILE + row * 144 + seg * 16;
        CP16(dst, src);
    }
}

__global__ void __launch_bounds__(256, 1)
attn_mma_kernel(const __half* __restrict__ QKVh, const __half* __restrict__ QKVl,
                float* __restrict__ Ob) {
    extern __shared__ char smem[];
    const uint32_t sb = (uint32_t)__cvta_generic_to_shared(smem);
    const int bh = blockIdx.y, b = bh / Hn, h = bh % Hn;
    const int i0 = blockIdx.x * 128;
    const int t = threadIdx.x, lane = t & 31, wid = t >> 5;

    const __half* Kh = QKVh;
    const __half* Kl = QKVl;
    const __half* Qh = QKVh + 1024;
    const __half* Ql = QKVl + 1024;
    const __half* Vh = QKVh + 2048;
    const __half* Vl = QKVl + 2048;

#pragma unroll
    for (int i = 0; i < 8; i++) {
        int c     = t + i * 256;
        int plane = c >> 10;
        int row   = (c >> 3) & 127;
        int seg   = c & 7;
        const __half* src = (plane ? Kl : Kh)
            + ((size_t)(i0 + row) * Bn + b) * QKVN + h * 64 + seg * 8;
        CP16(sb + plane * ATT_K_BYTES + row * 144 + seg * 16, src);
    }
    CP_COMMIT;
    attn_load_qv(sb, 0, 0, b, h, t, Qh, Ql, Vh, Vl);
    CP_COMMIT;

    CP_WAIT1;
    __syncthreads();

    uint32_t akh[4][4], akl[4][4];
    const uint32_t ka = sb + (uint32_t)((wid * 16 + ((lane >> 3) & 1) * 8 + (lane & 7)) * 144
                                        + (lane >> 4) * 16);
#pragma unroll
    for (int ks = 0; ks < 4; ks++) {
        ldsm4(akh[ks], ka + ks * 32);
        ldsm4(akl[ks], ka + ATT_K_BYTES + ks * 32);
    }

    float m0 = -1e30f, m1 = -1e30f, l0 = 0.f, l1 = 0.f;
    float o[8][4];
#pragma unroll
    for (int n = 0; n < 8; n++)
#pragma unroll
        for (int r = 0; r < 4; r++) o[n][r] = 0.f;

    const uint32_t qoff = (uint32_t)(((lane >> 4) * 8 + (lane & 7)) * 144
                                     + ((lane >> 3) & 1) * 16);
    const uint32_t voff = (uint32_t)((((lane >> 3) & 1) * 8 + (lane & 7)) * 144
                                     + (lane >> 4) * 16);
    const float scl = 0.03125f;

    for (int kt = 0; kt < 16; kt++) {
        if (kt < 15) {
            attn_load_qv(sb, (kt + 1) & 1, (kt + 1) * 64, b, h, t, Qh, Ql, Vh, Vl);
            CP_COMMIT;
            CP_WAIT1;
        } else {
            CP_WAIT0;
        }
        __syncthreads();
        const uint32_t qvb = sb + ATT_QV_BASE + (uint32_t)(kt & 1) * ATT_QV_STAGE;

        float s[8][4];
#pragma unroll
        for (int n = 0; n < 8; n++)
#pragma unroll
            for (int r = 0; r < 4; r++) s[n][r] = 0.f;

#pragma unroll
        for (int ks = 0; ks < 4; ks++) {
#pragma unroll
            for (int np = 0; np < 4; np++) {
                uint32_t qh[4], ql[4];
                const uint32_t qa = qvb + qoff + np * (16 * 144) + ks * 32;
                ldsm4(qh, qa);
                ldsm4(ql, qa + ATT_QV_TILE);
                mma16816(s[2 * np],     akh[ks], qh[0], qh[1]);
                mma16816(s[2 * np + 1], akh[ks], qh[2], qh[3]);
                mma16816(s[2 * np],     akh[ks], ql[0], ql[1]);
                mma16816(s[2 * np + 1], akh[ks], ql[2], ql[3]);
                mma16816(s[2 * np],     akl[ks], qh[0], qh[1]);
                mma16816(s[2 * np + 1], akl[ks], qh[2], qh[3]);
            }
        }

        float mt0 = -1e30f, mt1 = -1e30f;
#pragma unroll
        for (int n = 0; n < 8; n++) {
            s[n][0] *= scl; s[n][1] *= scl; s[n][2] *= scl; s[n][3] *= scl;
            mt0 = fmaxf(mt0, fmaxf(s[n][0], s[n][1]));
            mt1 = fmaxf(mt1, fmaxf(s[n][2], s[n][3]));
        }
        mt0 = fmaxf(mt0, __shfl_xor_sync(0xffffffffu, mt0, 1));
        mt0 = fmaxf(mt0, __shfl_xor_sync(0xffffffffu, mt0, 2));
        mt1 = fmaxf(mt1, __shfl_xor_sync(0xffffffffu, mt1, 1));
        mt1 = fmaxf(mt1, __shfl_xor_sync(0xffffffffu, mt1, 2));
        const float mn0 = fmaxf(m0, mt0), mn1 = fmaxf(m1, mt1);
        const float rs0 = __expf(m0 - mn0), rs1 = __expf(m1 - mn1);
        m0 = mn0; m1 = mn1;

        float ps0 = 0.f, ps1 = 0.f;
#pragma unroll
        for (int n = 0; n < 8; n++) {
            s[n][0] = __expf(s[n][0] - mn0);
            s[n][1] = __expf(s[n][1] - mn0);
            s[n][2] = __expf(s[n][2] - mn1);
            s[n][3] = __expf(s[n][3] - mn1);
            ps0 += s[n][0] + s[n][1];
            ps1 += s[n][2] + s[n][3];
        }
        ps0 += __shfl_xor_sync(0xffffffffu, ps0, 1);
        ps0 += __shfl_xor_sync(0xffffffffu, ps0, 2);
        ps1 += __shfl_xor_sync(0xffffffffu, ps1, 1);
        ps1 += __shfl_xor_sync(0xffffffffu, ps1, 2);
        l0 = l0 * rs0 + ps0;
        l1 = l1 * rs1 + ps1;
#pragma unroll
        for (int n = 0; n < 8; n++) {
            o[n][0] *= rs0; o[n][1] *= rs0;
            o[n][2] *= rs1; o[n][3] *= rs1;
        }

#pragma unroll
        for (int ki = 0; ki < 4; ki++) {
            __half hv[8], lv[8];
            splitf(s[2 * ki][0],     hv[0], lv[0]);
            splitf(s[2 * ki][1],     hv[1], lv[1]);
            splitf(s[2 * ki][2],     hv[2], lv[2]);
            splitf(s[2 * ki][3],     hv[3], lv[3]);
            splitf(s[2 * ki + 1][0], hv[4], lv[4]);
            splitf(s[2 * ki + 1][1], hv[5], lv[5]);
            splitf(s[2 * ki + 1][2], hv[6], lv[6]);
            splitf(s[2 * ki + 1][3], hv[7], lv[7]);
            uint32_t ph[4], pl[4];
            ph[0] = pack2(hv[0], hv[1]); ph[1] = pack2(hv[2], hv[3]);
            ph[2] = pack2(hv[4], hv[5]); ph[3] = pack2(hv[6], hv[7]);
            pl[0] = pack2(lv[0], lv[1]); pl[1] = pack2(lv[2], lv[3]);
            pl[2] = pack2(lv[4], lv[5]); pl[3] = pack2(lv[6], lv[7]);

#pragma unroll
            for (int np = 0; np < 4; np++) {
                uint32_t vh[4], vl[4];
                const uint32_t va = qvb + 2 * ATT_QV_TILE + voff
                                  + ki * (16 * 144) + np * 32;
                ldsm4t(vh, va);
                ldsm4t(vl, va + ATT_QV_TILE);
                mma16816(o[2 * np],     ph, vh[0], vh[1]);
                mma16816(o[2 * np + 1], ph, vh[2], vh[3]);
                mma16816(o[2 * np],     ph, vl[0], vl[1]);
                mma16816(o[2 * np + 1], ph, vl[2], vl[3]);
                mma16816(o[2 * np],     pl, vh[0], vh[1]);
                mma16816(o[2 * np + 1], pl, vh[2], vh[3]);
            }
        }
        __syncthreads();
    }

    const float inv0 = 1.0f / l0, inv1 = 1.0f / l1;
    const int row0 = i0 + wid * 16 + (lane >> 2);
    const int colb = h * 64 + (lane & 3) * 2;
#pragma unroll
    for (int n = 0; n < 8; n++) {
        float2 w0 = {o[n][0] * inv0, o[n][1] * inv0};
        float2 w1 = {o[n][2] * inv1, o[n][3] * inv1};
        *(float2*)(Ob + ((size_t)row0 * Bn + b) * HDQK + colb + n * 8) = w0;
        *(float2*)(Ob + ((size_t)(row0 + 8) * Bn + b) * HDQK + colb + n * 8) = w1;
    }
}

// ------------------------- host driver --------------------------------------
extern "C" void kernel_launch(void* const* d_in, const int* in_sizes, int n_in,
                              void* d_out, int out_size) {
    (void)in_sizes; (void)n_in; (void)out_size;

    const float* x_in = (const float*)d_in[0];
    const float* Wk = (const float*)d_in[2];
    const float* bk = (const float*)d_in[3];
    const float* Wq = (const float*)d_in[4];
    const float* bq = (const float*)d_in[5];
    const float* Wv = (const float*)d_in[6];
    const float* bv = (const float*)d_in[7];
    const float* W1 = (const float*)d_in[8];
    const float* b1 = (const float*)d_in[9];
    const float* W2 = (const float*)d_in[10];
    const float* b2 = (const float*)d_in[11];

    float *px, *pz, *pf, *pa, *pbq;
    cudaGetSymbolAddress((void**)&px, g_x);
    cudaGetSymbolAddress((void**)&pz, g_z);
    cudaGetSymbolAddress((void**)&pf, g_f);
    cudaGetSymbolAddress((void**)&pa, g_att);
    cudaGetSymbolAddress((void**)&pbq, g_bqkv);

    __half *xh, *zh, *hh, *qkh, *qkl;
    __half *wqh, *wql, *w1h, *w1l, *w2h, *w2l;
    cudaGetSymbolAddress((void**)&xh, g_xh);
    cudaGetSymbolAddress((void**)&zh, g_zh);
    cudaGetSymbolAddress((void**)&hh, g_hh);
    cudaGetSymbolAddress((void**)&qkh, g_qkvh); cudaGetSymbolAddress((void**)&qkl, g_qkvl);
    cudaGetSymbolAddress((void**)&wqh, g_wqkvh); cudaGetSymbolAddress((void**)&wql, g_wqkvl);
    cudaGetSymbolAddress((void**)&w1h, g_w1h);   cudaGetSymbolAddress((void**)&w1l, g_w1l);
    cudaGetSymbolAddress((void**)&w2h, g_w2h);   cudaGetSymbolAddress((void**)&w2l, g_w2l);

    cudaFuncSetAttribute(gemm_mma_kernel<1>,
                         cudaFuncAttributeMaxDynamicSharedMemorySize, GEMM_SMEM);
    cudaFuncSetAttribute(gemm_mma_kernel<2>,
                         cudaFuncAttributeMaxDynamicSharedMemorySize, GEMM_SMEM);
    cudaFuncSetAttribute(gemm_mma_kernel<3>,
                         cudaFuncAttributeMaxDynamicSharedMemorySize, GEMM_SMEM);
    cudaFuncSetAttribute(attn_mma_kernel,
                         cudaFuncAttributeMaxDynamicSharedMemorySize, ATT2_SMEM);

    const dim3 blk(256);

    // 5 setup launches
    cvt1_kernel<<<NTOK * Dn / 1024, blk>>>(x_in, xh, NTOK * Dn / 4);
    cvt_qkv_kernel<<<dim3(Ln * Dn * 1024 / 1024, 3), blk>>>(Wk, Wq, Wv, wqh, wql);
    cvt_pair_kernel<<<Ln * Dn * FFn / 1024, blk>>>(W1, w1h, w1l, Ln * Dn * FFn / 4);
    cvt_pair_kernel<<<Ln * FFn * Dn / 1024, blk>>>(W2, w2h, w2l, Ln * FFn * Dn / 4);
    combine_bias_kernel<<<Ln * QKVN / 256, blk>>>(bk, bq, bv, pbq);

    const dim3 gFF1(FFn / BN, NTOK / BM);    // (32, 32)
    const dim3 gFF2(Dn  / BN, NTOK / BM);    // (8, 32)
    const dim3 gQKV(QKVN / BN, NTOK / BM);   // (24, 32)
    const dim3 gATT(Tn / 128, Bn * Hn);      // (8, 64)

    for (int l = 0; l < Ln; l++) {
        const float* xl32 = (l == 0) ? x_in : px;

        gemm_mma_kernel<1><<<gFF1, blk, GEMM_SMEM>>>(
            xh, w1h + (size_t)l * Dn * FFn, w1l + (size_t)l * Dn * FFn,
            b1 + (size_t)l * FFn, nullptr, hh, nullptr, NTOK, Dn, FFn);
        gemm_mma_kernel<2><<<gFF2, blk, GEMM_SMEM>>>(
            hh, w2h + (size_t)l * FFn * Dn, w2l + (size_t)l * FFn * Dn,
            b2 + (size_t)l * Dn, pf, nullptr, nullptr, NTOK, FFn, Dn);

        resnorm_kernel<<<NTOK, blk>>>(xl32, pf, pz, zh);

        gemm_mma_kernel<3><<<gQKV, blk, GEMM_SMEM>>>(
            zh, wqh + (size_t)l * Dn * QKVN, wql + (size_t)l * Dn * QKVN,
            pbq + (size_t)l * QKVN, nullptr, qkh, qkl, NTOK, Dn, QKVN);

        attn_mma_kernel<<<gATT, blk, ATT2_SMEM>>>(qkh, qkl, pa);

        float* xout = (l == Ln - 1) ? (float*)d_out : px;
        resnorm_kernel<<<NTOK, blk>>>(pz, pa, xout, xh);
    }
}